// round 5
// baseline (speedup 1.0000x reference)
#include <cuda_runtime.h>
#include <cuda_fp16.h>
#include <math.h>
#include <stdint.h>

#define B_TOK 8192
#define D_DIM 1024
#define E_NUM 8

// ---------------- scratch (device globals; no allocs allowed) ----------------
__device__ int    g_counts[E_NUM];
__device__ int    g_bucket_tok [E_NUM * B_TOK];
__device__ int    g_bucket_slot[E_NUM * B_TOK];
__device__ float  g_gate[B_TOK * 2];
__device__ float  g_partial[(size_t)B_TOK * 2 * D_DIM];       // exp(expert_out) per slot
__device__ __half g_xhi[(size_t)B_TOK * D_DIM];
__device__ __half g_xlo[(size_t)B_TOK * D_DIM];
__device__ __half g_whi[(size_t)E_NUM * D_DIM * D_DIM];       // W^T hi, [E][N][K]
__device__ __half g_wlo[(size_t)E_NUM * D_DIM * D_DIM];       // W^T lo, [E][N][K]

// ---------------- PTX helpers (sm_80-baseline only) ----------------
__device__ __forceinline__ uint32_t smem_u32(const void* p) {
    uint32_t a;
    asm("{ .reg .u64 t; cvta.to.shared.u64 t, %1; cvt.u32.u64 %0, t; }" : "=r"(a) : "l"(p));
    return a;
}

#define CP16(dst, src) \
    asm volatile("cp.async.cg.shared.global [%0], [%1], 16;" \
        :: "r"(dst), "l"(__cvta_generic_to_global(src)) : "memory")
#define CP_COMMIT() asm volatile("cp.async.commit_group;" ::: "memory")
#define CP_WAIT1()  asm volatile("cp.async.wait_group 1;" ::: "memory")
#define CP_WAIT0()  asm volatile("cp.async.wait_group 0;" ::: "memory")

#define LDSM4(r, addr) \
    asm volatile("ldmatrix.sync.aligned.m8n8.x4.shared.b16 {%0,%1,%2,%3}, [%4];" \
        : "=r"((r)[0]), "=r"((r)[1]), "=r"((r)[2]), "=r"((r)[3]) : "r"(addr))

#define MMA16816(d, a, b0, b1) \
    asm volatile("mma.sync.aligned.m16n8k16.row.col.f32.f16.f16.f32 " \
        "{%0,%1,%2,%3}, {%4,%5,%6,%7}, {%8,%9}, {%0,%1,%2,%3};" \
        : "+f"((d)[0]), "+f"((d)[1]), "+f"((d)[2]), "+f"((d)[3]) \
        : "r"((a)[0]), "r"((a)[1]), "r"((a)[2]), "r"((a)[3]), "r"(b0), "r"(b1))

#define SWZ(row, chunk) ((uint32_t)((row) * 128 + (((chunk) ^ ((row) & 7)) << 4)))

// ---------------- kernel 0: zero bucket counts ----------------
__global__ void zero_counts_kernel() {
    if (threadIdx.x < E_NUM) g_counts[threadIdx.x] = 0;
}

__device__ __forceinline__ float softplus_stable(float z) {
    return fmaxf(z, 0.0f) + log1pf(expf(-fabsf(z)));
}

// ---------------- kernel 1: gating + x split (1 warp per token) ----------------
__global__ void gating_kernel(const float* __restrict__ x,
                              const float* __restrict__ noise,
                              const float* __restrict__ w_gate,
                              const float* __restrict__ w_noise) {
    const int warp = threadIdx.x >> 5;
    const int lane = threadIdx.x & 31;
    const int b = blockIdx.x * 8 + warp;
    if (b >= B_TOK) return;

    float accC[8] = {0.f,0.f,0.f,0.f,0.f,0.f,0.f,0.f};
    float accN[8] = {0.f,0.f,0.f,0.f,0.f,0.f,0.f,0.f};
    const float* xr = x + (size_t)b * D_DIM;
    __half2* xh = (__half2*)(g_xhi + (size_t)b * D_DIM);
    __half2* xl = (__half2*)(g_xlo + (size_t)b * D_DIM);

    #pragma unroll
    for (int i = 0; i < 16; i++) {
        int d = 2 * lane + 64 * i;
        float2 v = *(const float2*)(xr + d);

        __half h0 = __float2half_rn(v.x), h1 = __float2half_rn(v.y);
        __half l0 = __float2half_rn(v.x - __half2float(h0));
        __half l1 = __float2half_rn(v.y - __half2float(h1));
        xh[d >> 1] = __halves2half2(h0, h1);
        xl[d >> 1] = __halves2half2(l0, l1);

        const float4* wg0 = reinterpret_cast<const float4*>(w_gate  + (size_t)d * 8);
        const float4* wn0 = reinterpret_cast<const float4*>(w_noise + (size_t)d * 8);
        float4 ga = wg0[0], gb = wg0[1], gc = wg0[2], gd = wg0[3];
        float4 na = wn0[0], nb = wn0[1], nc = wn0[2], nd = wn0[3];
        accC[0] = fmaf(v.x, ga.x, accC[0]); accC[1] = fmaf(v.x, ga.y, accC[1]);
        accC[2] = fmaf(v.x, ga.z, accC[2]); accC[3] = fmaf(v.x, ga.w, accC[3]);
        accC[4] = fmaf(v.x, gb.x, accC[4]); accC[5] = fmaf(v.x, gb.y, accC[5]);
        accC[6] = fmaf(v.x, gb.z, accC[6]); accC[7] = fmaf(v.x, gb.w, accC[7]);
        accC[0] = fmaf(v.y, gc.x, accC[0]); accC[1] = fmaf(v.y, gc.y, accC[1]);
        accC[2] = fmaf(v.y, gc.z, accC[2]); accC[3] = fmaf(v.y, gc.w, accC[3]);
        accC[4] = fmaf(v.y, gd.x, accC[4]); accC[5] = fmaf(v.y, gd.y, accC[5]);
        accC[6] = fmaf(v.y, gd.z, accC[6]); accC[7] = fmaf(v.y, gd.w, accC[7]);
        accN[0] = fmaf(v.x, na.x, accN[0]); accN[1] = fmaf(v.x, na.y, accN[1]);
        accN[2] = fmaf(v.x, na.z, accN[2]); accN[3] = fmaf(v.x, na.w, accN[3]);
        accN[4] = fmaf(v.x, nb.x, accN[4]); accN[5] = fmaf(v.x, nb.y, accN[5]);
        accN[6] = fmaf(v.x, nb.z, accN[6]); accN[7] = fmaf(v.x, nb.w, accN[7]);
        accN[0] = fmaf(v.y, nc.x, accN[0]); accN[1] = fmaf(v.y, nc.y, accN[1]);
        accN[2] = fmaf(v.y, nc.z, accN[2]); accN[3] = fmaf(v.y, nc.w, accN[3]);
        accN[4] = fmaf(v.y, nd.x, accN[4]); accN[5] = fmaf(v.y, nd.y, accN[5]);
        accN[6] = fmaf(v.y, nd.z, accN[6]); accN[7] = fmaf(v.y, nd.w, accN[7]);
    }

    #pragma unroll
    for (int e = 0; e < 8; e++) {
        #pragma unroll
        for (int off = 16; off > 0; off >>= 1) {
            accC[e] += __shfl_xor_sync(0xffffffffu, accC[e], off);
            accN[e] += __shfl_xor_sync(0xffffffffu, accN[e], off);
        }
    }

    if (lane == 0) {
        float logits[8];
        #pragma unroll
        for (int e = 0; e < 8; e++) {
            float sd = softplus_stable(accN[e]) + 0.01f;
            logits[e] = fmaf(noise[(size_t)b * E_NUM + e], sd, accC[e]);
        }
        int i0 = 0; float v0 = logits[0];
        #pragma unroll
        for (int e = 1; e < 8; e++) { if (logits[e] > v0) { v0 = logits[e]; i0 = e; } }
        int i1 = -1; float v1 = -INFINITY;
        #pragma unroll
        for (int e = 0; e < 8; e++) {
            if (e != i0 && logits[e] > v1) { v1 = logits[e]; i1 = e; }
        }
        float ex = expf(v1 - v0);
        float inv = 1.0f / (1.0f + ex);
        g_gate[b * 2 + 0] = inv;
        g_gate[b * 2 + 1] = ex * inv;

        int p0 = atomicAdd(&g_counts[i0], 1);
        g_bucket_tok [i0 * B_TOK + p0] = b;
        g_bucket_slot[i0 * B_TOK + p0] = b * 2 + 0;
        int p1 = atomicAdd(&g_counts[i1], 1);
        g_bucket_tok [i1 * B_TOK + p1] = b;
        g_bucket_slot[i1 * B_TOK + p1] = b * 2 + 1;
    }
}

// ---------------- kernel 2: transpose + fp16 hi/lo split of W ----------------
__global__ __launch_bounds__(256)
void prep_w_kernel(const float* __restrict__ W) {
    __shared__ float tile[32][33];
    const int e  = blockIdx.z;
    const int k0 = blockIdx.y * 32;
    const int n0 = blockIdx.x * 32;
    const int tx = threadIdx.x;
    const int ty = threadIdx.y;
    const float* We = W + (size_t)e * D_DIM * D_DIM;

    #pragma unroll
    for (int i = 0; i < 32; i += 8)
        tile[ty + i][tx] = We[(size_t)(k0 + ty + i) * D_DIM + n0 + tx];
    __syncthreads();

    #pragma unroll
    for (int i = 0; i < 32; i += 8) {
        float v = tile[tx][ty + i];
        __half hi = __float2half_rn(v);
        __half lo = __float2half_rn(v - __half2float(hi));
        size_t o = ((size_t)(e * D_DIM + n0 + ty + i)) * D_DIM + k0 + tx;
        g_whi[o] = hi;
        g_wlo[o] = lo;
    }
}

// ---------------- kernel 3: routed 3-pass fp16 mma.sync GEMM ----------------
// 512 threads, 4x4 warp grid, 32x32 warp tiles, 3-stage cp.async pipeline
#define BMh 128
#define BNh 128
#define BKh 64
#define NCHUNK (D_DIM / BKh)           // 16
#define STG 65536
#define OFF_ALO 16384
#define OFF_BHI 32768
#define OFF_BLO 49152
#define NSTAGE 3
#define NTHR 512
#define SMEM_GEMM (1024 + NSTAGE * STG)

__device__ __forceinline__ void load_stage(uint32_t sbuf, const int* stok,
                                           const __half* __restrict__ wh,
                                           const __half* __restrict__ wl,
                                           int kt, int tid) {
    #pragma unroll
    for (int i = 0; i < 2; i++) {
        int lin = i * NTHR + tid;
        int row = lin >> 3, ch = lin & 7;
        int tok = stok[row];
        const __half* sa = g_xhi + (size_t)tok * D_DIM + kt + ch * 8;
        const __half* sl = g_xlo + (size_t)tok * D_DIM + kt + ch * 8;
        uint32_t d = sbuf + SWZ(row, ch);
        CP16(d, sa);
        CP16(d + OFF_ALO, sl);
    }
    #pragma unroll
    for (int i = 0; i < 2; i++) {
        int lin = i * NTHR + tid;
        int row = lin >> 3, ch = lin & 7;
        const __half* sb = wh + (size_t)row * D_DIM + kt + ch * 8;
        const __half* sl = wl + (size_t)row * D_DIM + kt + ch * 8;
        uint32_t d = sbuf + OFF_BHI + SWZ(row, ch);
        CP16(d, sb);
        CP16(d + 16384, sl);
    }
}

__global__ __launch_bounds__(NTHR, 1)
void expert_hmma_kernel(const float* __restrict__ bias) {
    const int e     = blockIdx.z;
    const int count = g_counts[e];
    const int m0    = blockIdx.y * BMh;
    if (m0 >= count) return;
    const int n0    = blockIdx.x * BNh;

    extern __shared__ char smraw[];
    int* stok  = (int*)smraw;            // [128]
    int* sslot = (int*)(smraw + 512);    // [128]
    const uint32_t sbase = smem_u32(smraw) + 1024;
    uint32_t sbuf3[NSTAGE];
    #pragma unroll
    for (int s = 0; s < NSTAGE; s++) sbuf3[s] = sbase + s * STG;

    const int tid  = threadIdx.x;
    const int wid  = tid >> 5;
    const int lane = tid & 31;
    const int wm   = (wid & 3) * 32;     // warp m offset (4 warps over 128)
    const int wn   = (wid >> 2) * 32;    // warp n offset (4 warps over 128)

    if (tid < BMh) {
        int m = m0 + tid;
        bool ok = (m < count);
        stok [tid] = ok ? g_bucket_tok [e * B_TOK + m] : 0;
        sslot[tid] = ok ? g_bucket_slot[e * B_TOK + m] : -1;
    }
    __syncthreads();

    const __half* wh = g_whi + ((size_t)e * D_DIM + n0) * D_DIM;
    const __half* wl = g_wlo + ((size_t)e * D_DIM + n0) * D_DIM;

    float acc[2][4][4];
    #pragma unroll
    for (int mt = 0; mt < 2; mt++)
        #pragma unroll
        for (int nt = 0; nt < 4; nt++)
            #pragma unroll
            for (int c = 0; c < 4; c++) acc[mt][nt][c] = 0.0f;

    load_stage(sbuf3[0], stok, wh, wl, 0, tid);
    CP_COMMIT();
    load_stage(sbuf3[1], stok, wh, wl, BKh, tid);
    CP_COMMIT();

    const int lrow = lane & 15;
    const int lsel = lane >> 4;

    int sidx = 0;
    int pidx = 2;
    for (int c = 0; c < NCHUNK; c++) {
        if (c == NCHUNK - 1) { CP_WAIT0(); } else { CP_WAIT1(); }
        __syncthreads();
        if (c + 2 < NCHUNK) {
            load_stage(sbuf3[pidx], stok, wh, wl, (c + 2) * BKh, tid);
            CP_COMMIT();
        }

        const uint32_t sbuf = sbuf3[sidx];
        #pragma unroll
        for (int ks = 0; ks < 4; ks++) {
            const int chunk = ks * 2 + lsel;
            uint32_t ahi[2][4], alo[2][4];
            #pragma unroll
            for (int mt = 0; mt < 2; mt++) {
                int r = wm + mt * 16 + lrow;
                uint32_t ad = sbuf + SWZ(r, chunk);
                LDSM4(ahi[mt], ad);
                LDSM4(alo[mt], ad + OFF_ALO);
            }
            uint32_t bhi[2][4], blo[2][4];
            #pragma unroll
            for (int ng = 0; ng < 2; ng++) {
                int r = wn + ng * 16 + lrow;
                uint32_t bd = sbuf + OFF_BHI + SWZ(r, chunk);
                LDSM4(bhi[ng], bd);
                LDSM4(blo[ng], bd + 16384);
            }
            #pragma unroll
            for (int mt = 0; mt < 2; mt++)
                #pragma unroll
                for (int nt = 0; nt < 4; nt++) {
                    int ng = nt >> 1, o = nt & 1;
                    MMA16816(acc[mt][nt], ahi[mt], bhi[ng][o], bhi[ng][2 + o]);
                    MMA16816(acc[mt][nt], ahi[mt], blo[ng][o], blo[ng][2 + o]);
                    MMA16816(acc[mt][nt], alo[mt], bhi[ng][o], bhi[ng][2 + o]);
                }
        }

        sidx = (sidx + 1 == NSTAGE) ? 0 : sidx + 1;
        pidx = (pidx + 1 == NSTAGE) ? 0 : pidx + 1;
    }

    // epilogue: fused bias + exp, scatter to per-slot partials
    #pragma unroll
    for (int mt = 0; mt < 2; mt++) {
        #pragma unroll
        for (int h = 0; h < 2; h++) {
            int m = wm + mt * 16 + (lane >> 2) + h * 8;
            int slot = sslot[m];
            if (slot < 0) continue;
            float* pr = g_partial + ((size_t)slot << 10);
            #pragma unroll
            for (int nt = 0; nt < 4; nt++) {
                int col = n0 + wn + nt * 8 + (lane & 3) * 2;
                float2 bv = *(const float2*)(bias + (size_t)e * D_DIM + col);
                float2 o;
                o.x = expf(acc[mt][nt][h * 2 + 0] + bv.x);
                o.y = expf(acc[mt][nt][h * 2 + 1] + bv.y);
                *(float2*)(pr + col) = o;
            }
        }
    }
}

// ---------------- kernel 4: combine ----------------
__global__ void combine_kernel(float* __restrict__ out) {
    int idx = blockIdx.x * 256 + threadIdx.x;
    int b = idx >> 8;
    int h4 = (idx & 255) << 2;
    float g0 = g_gate[b * 2 + 0];
    float g1 = g_gate[b * 2 + 1];
    float4 p0 = *(const float4*)(g_partial + ((size_t)(b * 2 + 0) << 10) + h4);
    float4 p1 = *(const float4*)(g_partial + ((size_t)(b * 2 + 1) << 10) + h4);
    float4 o;
    float c0 = fmaf(g0, p0.x, g1 * p1.x);
    float c1 = fmaf(g0, p0.y, g1 * p1.y);
    float c2 = fmaf(g0, p0.z, g1 * p1.z);
    float c3 = fmaf(g0, p0.w, g1 * p1.w);
    const float EPSF = 2.2204460492503131e-16f;
    o.x = logf(c0 == 0.0f ? EPSF : c0);
    o.y = logf(c1 == 0.0f ? EPSF : c1);
    o.z = logf(c2 == 0.0f ? EPSF : c2);
    o.w = logf(c3 == 0.0f ? EPSF : c3);
    *(float4*)(out + (size_t)b * D_DIM + h4) = o;
}

// ---------------- launch ----------------
extern "C" void kernel_launch(void* const* d_in, const int* in_sizes, int n_in,
                              void* d_out, int out_size) {
    const float* x         = (const float*)d_in[0];
    const float* noise     = (const float*)d_in[1];
    const float* w_gate    = (const float*)d_in[2];
    const float* w_noise   = (const float*)d_in[3];
    const float* W_experts = (const float*)d_in[4];
    const float* b_experts = (const float*)d_in[5];
    float* out = (float*)d_out;

    cudaFuncSetAttribute(expert_hmma_kernel,
                         cudaFuncAttributeMaxDynamicSharedMemorySize, SMEM_GEMM);

    zero_counts_kernel<<<1, 32>>>();
    gating_kernel<<<B_TOK / 8, 256>>>(x, noise, w_gate, w_noise);

    dim3 pgrid(D_DIM / 32, D_DIM / 32, E_NUM);
    prep_w_kernel<<<pgrid, dim3(32, 8, 1)>>>(W_experts);

    dim3 ggrid(D_DIM / BNh, B_TOK / BMh, E_NUM);  // (8, 64, 8)
    expert_hmma_kernel<<<ggrid, NTHR, SMEM_GEMM>>>(b_experts);

    combine_kernel<<<(B_TOK * D_DIM / 4) / 256, 256>>>(out);
}

// round 6
// speedup vs baseline: 1.2578x; 1.2578x over previous
#include <cuda_runtime.h>
#include <cuda_fp16.h>
#include <math.h>
#include <stdint.h>

#define B_TOK 8192
#define D_DIM 1024
#define E_NUM 8

// ---------------- scratch (device globals; no allocs allowed) ----------------
__device__ int    g_counts[E_NUM];
__device__ int    g_bucket_tok [E_NUM * B_TOK];
__device__ int    g_bucket_slot[E_NUM * B_TOK];
__device__ float  g_gate[B_TOK * 2];
__device__ float  g_partial[(size_t)B_TOK * 2 * D_DIM];       // exp(expert_out) per slot
__device__ __half g_xhi[(size_t)B_TOK * D_DIM];
__device__ __half g_whi[(size_t)E_NUM * D_DIM * D_DIM];       // W^T hi, [E][N][K]
__device__ __half g_wlo[(size_t)E_NUM * D_DIM * D_DIM];       // W^T lo, [E][N][K]

// ---------------- PTX helpers (sm_80-baseline only) ----------------
__device__ __forceinline__ uint32_t smem_u32(const void* p) {
    uint32_t a;
    asm("{ .reg .u64 t; cvta.to.shared.u64 t, %1; cvt.u32.u64 %0, t; }" : "=r"(a) : "l"(p));
    return a;
}

#define CP16(dst, src) \
    asm volatile("cp.async.cg.shared.global [%0], [%1], 16;" \
        :: "r"(dst), "l"(__cvta_generic_to_global(src)) : "memory")
#define CP_COMMIT() asm volatile("cp.async.commit_group;" ::: "memory")
#define CP_WAIT1()  asm volatile("cp.async.wait_group 1;" ::: "memory")
#define CP_WAIT0()  asm volatile("cp.async.wait_group 0;" ::: "memory")

#define LDSM4(r, addr) \
    asm volatile("ldmatrix.sync.aligned.m8n8.x4.shared.b16 {%0,%1,%2,%3}, [%4];" \
        : "=r"((r)[0]), "=r"((r)[1]), "=r"((r)[2]), "=r"((r)[3]) : "r"(addr))

#define MMA16816(d, a, b0, b1) \
    asm volatile("mma.sync.aligned.m16n8k16.row.col.f32.f16.f16.f32 " \
        "{%0,%1,%2,%3}, {%4,%5,%6,%7}, {%8,%9}, {%0,%1,%2,%3};" \
        : "+f"((d)[0]), "+f"((d)[1]), "+f"((d)[2]), "+f"((d)[3]) \
        : "r"((a)[0]), "r"((a)[1]), "r"((a)[2]), "r"((a)[3]), "r"(b0), "r"(b1))

#define SWZ(row, chunk) ((uint32_t)((row) * 128 + (((chunk) ^ ((row) & 7)) << 4)))

// ---------------- kernel 0: zero bucket counts ----------------
__global__ void zero_counts_kernel() {
    if (threadIdx.x < E_NUM) g_counts[threadIdx.x] = 0;
}

__device__ __forceinline__ float softplus_stable(float z) {
    return fmaxf(z, 0.0f) + log1pf(expf(-fabsf(z)));
}

// ---------------- kernel 1: gating + x hi-split (1 warp per token) ----------------
__global__ void gating_kernel(const float* __restrict__ x,
                              const float* __restrict__ noise,
                              const float* __restrict__ w_gate,
                              const float* __restrict__ w_noise) {
    const int warp = threadIdx.x >> 5;
    const int lane = threadIdx.x & 31;
    const int b = blockIdx.x * 8 + warp;
    if (b >= B_TOK) return;

    float accC[8] = {0.f,0.f,0.f,0.f,0.f,0.f,0.f,0.f};
    float accN[8] = {0.f,0.f,0.f,0.f,0.f,0.f,0.f,0.f};
    const float* xr = x + (size_t)b * D_DIM;
    __half2* xh = (__half2*)(g_xhi + (size_t)b * D_DIM);

    #pragma unroll
    for (int i = 0; i < 16; i++) {
        int d = 2 * lane + 64 * i;
        float2 v = *(const float2*)(xr + d);

        xh[d >> 1] = __halves2half2(__float2half_rn(v.x), __float2half_rn(v.y));

        const float4* wg0 = reinterpret_cast<const float4*>(w_gate  + (size_t)d * 8);
        const float4* wn0 = reinterpret_cast<const float4*>(w_noise + (size_t)d * 8);
        float4 ga = wg0[0], gb = wg0[1], gc = wg0[2], gd = wg0[3];
        float4 na = wn0[0], nb = wn0[1], nc = wn0[2], nd = wn0[3];
        accC[0] = fmaf(v.x, ga.x, accC[0]); accC[1] = fmaf(v.x, ga.y, accC[1]);
        accC[2] = fmaf(v.x, ga.z, accC[2]); accC[3] = fmaf(v.x, ga.w, accC[3]);
        accC[4] = fmaf(v.x, gb.x, accC[4]); accC[5] = fmaf(v.x, gb.y, accC[5]);
        accC[6] = fmaf(v.x, gb.z, accC[6]); accC[7] = fmaf(v.x, gb.w, accC[7]);
        accC[0] = fmaf(v.y, gc.x, accC[0]); accC[1] = fmaf(v.y, gc.y, accC[1]);
        accC[2] = fmaf(v.y, gc.z, accC[2]); accC[3] = fmaf(v.y, gc.w, accC[3]);
        accC[4] = fmaf(v.y, gd.x, accC[4]); accC[5] = fmaf(v.y, gd.y, accC[5]);
        accC[6] = fmaf(v.y, gd.z, accC[6]); accC[7] = fmaf(v.y, gd.w, accC[7]);
        accN[0] = fmaf(v.x, na.x, accN[0]); accN[1] = fmaf(v.x, na.y, accN[1]);
        accN[2] = fmaf(v.x, na.z, accN[2]); accN[3] = fmaf(v.x, na.w, accN[3]);
        accN[4] = fmaf(v.x, nb.x, accN[4]); accN[5] = fmaf(v.x, nb.y, accN[5]);
        accN[6] = fmaf(v.x, nb.z, accN[6]); accN[7] = fmaf(v.x, nb.w, accN[7]);
        accN[0] = fmaf(v.y, nc.x, accN[0]); accN[1] = fmaf(v.y, nc.y, accN[1]);
        accN[2] = fmaf(v.y, nc.z, accN[2]); accN[3] = fmaf(v.y, nc.w, accN[3]);
        accN[4] = fmaf(v.y, nd.x, accN[4]); accN[5] = fmaf(v.y, nd.y, accN[5]);
        accN[6] = fmaf(v.y, nd.z, accN[6]); accN[7] = fmaf(v.y, nd.w, accN[7]);
    }

    #pragma unroll
    for (int e = 0; e < 8; e++) {
        #pragma unroll
        for (int off = 16; off > 0; off >>= 1) {
            accC[e] += __shfl_xor_sync(0xffffffffu, accC[e], off);
            accN[e] += __shfl_xor_sync(0xffffffffu, accN[e], off);
        }
    }

    if (lane == 0) {
        float logits[8];
        #pragma unroll
        for (int e = 0; e < 8; e++) {
            float sd = softplus_stable(accN[e]) + 0.01f;
            logits[e] = fmaf(noise[(size_t)b * E_NUM + e], sd, accC[e]);
        }
        int i0 = 0; float v0 = logits[0];
        #pragma unroll
        for (int e = 1; e < 8; e++) { if (logits[e] > v0) { v0 = logits[e]; i0 = e; } }
        int i1 = -1; float v1 = -INFINITY;
        #pragma unroll
        for (int e = 0; e < 8; e++) {
            if (e != i0 && logits[e] > v1) { v1 = logits[e]; i1 = e; }
        }
        float ex = expf(v1 - v0);
        float inv = 1.0f / (1.0f + ex);
        g_gate[b * 2 + 0] = inv;
        g_gate[b * 2 + 1] = ex * inv;

        int p0 = atomicAdd(&g_counts[i0], 1);
        g_bucket_tok [i0 * B_TOK + p0] = b;
        g_bucket_slot[i0 * B_TOK + p0] = b * 2 + 0;
        int p1 = atomicAdd(&g_counts[i1], 1);
        g_bucket_tok [i1 * B_TOK + p1] = b;
        g_bucket_slot[i1 * B_TOK + p1] = b * 2 + 1;
    }
}

// ---------------- kernel 2: transpose + fp16 hi/lo split of W ----------------
__global__ __launch_bounds__(256)
void prep_w_kernel(const float* __restrict__ W) {
    __shared__ float tile[32][33];
    const int e  = blockIdx.z;
    const int k0 = blockIdx.y * 32;
    const int n0 = blockIdx.x * 32;
    const int tx = threadIdx.x;
    const int ty = threadIdx.y;
    const float* We = W + (size_t)e * D_DIM * D_DIM;

    #pragma unroll
    for (int i = 0; i < 32; i += 8)
        tile[ty + i][tx] = We[(size_t)(k0 + ty + i) * D_DIM + n0 + tx];
    __syncthreads();

    #pragma unroll
    for (int i = 0; i < 32; i += 8) {
        float v = tile[tx][ty + i];
        __half hi = __float2half_rn(v);
        __half lo = __float2half_rn(v - __half2float(hi));
        size_t o = ((size_t)(e * D_DIM + n0 + ty + i)) * D_DIM + k0 + tx;
        g_whi[o] = hi;
        g_wlo[o] = lo;
    }
}

// ---------------- kernel 3: routed 2-pass fp16 mma.sync GEMM ----------------
// D = Ahi*(Bhi + Blo); A at fp16-hi precision, B fully split.
#define BMh 128
#define BNh 128
#define BKh 64
#define NCHUNK (D_DIM / BKh)           // 16
#define STG 49152                      // Ahi 16K | Bhi 16K | Blo 16K
#define OFF_BHI 16384
#define OFF_BLO 32768
#define NSTAGE 3
#define NTHR 512
#define SMEM_GEMM (1024 + NSTAGE * STG)

__device__ __forceinline__ void load_stage(uint32_t sbuf, const int* stok,
                                           const __half* __restrict__ wh,
                                           const __half* __restrict__ wl,
                                           int kt, int tid) {
    #pragma unroll
    for (int i = 0; i < 2; i++) {
        int lin = i * NTHR + tid;
        int row = lin >> 3, ch = lin & 7;
        int tok = stok[row];
        const __half* sa = g_xhi + (size_t)tok * D_DIM + kt + ch * 8;
        CP16(sbuf + SWZ(row, ch), sa);
    }
    #pragma unroll
    for (int i = 0; i < 2; i++) {
        int lin = i * NTHR + tid;
        int row = lin >> 3, ch = lin & 7;
        const __half* sb = wh + (size_t)row * D_DIM + kt + ch * 8;
        const __half* sl = wl + (size_t)row * D_DIM + kt + ch * 8;
        uint32_t d = sbuf + OFF_BHI + SWZ(row, ch);
        CP16(d, sb);
        CP16(d + 16384, sl);
    }
}

__global__ __launch_bounds__(NTHR, 1)
void expert_hmma_kernel(const float* __restrict__ bias) {
    const int e     = blockIdx.z;
    const int count = g_counts[e];
    const int m0    = blockIdx.y * BMh;
    if (m0 >= count) return;
    const int n0    = blockIdx.x * BNh;

    extern __shared__ char smraw[];
    int* stok  = (int*)smraw;            // [128]
    int* sslot = (int*)(smraw + 512);    // [128]
    const uint32_t sbase = smem_u32(smraw) + 1024;
    uint32_t sbuf3[NSTAGE];
    #pragma unroll
    for (int s = 0; s < NSTAGE; s++) sbuf3[s] = sbase + s * STG;

    const int tid  = threadIdx.x;
    const int wid  = tid >> 5;
    const int lane = tid & 31;
    const int wm   = (wid & 3) * 32;     // warp m offset (4 warps over 128)
    const int wn   = (wid >> 2) * 32;    // warp n offset (4 warps over 128)

    if (tid < BMh) {
        int m = m0 + tid;
        bool ok = (m < count);
        stok [tid] = ok ? g_bucket_tok [e * B_TOK + m] : 0;
        sslot[tid] = ok ? g_bucket_slot[e * B_TOK + m] : -1;
    }
    __syncthreads();

    const __half* wh = g_whi + ((size_t)e * D_DIM + n0) * D_DIM;
    const __half* wl = g_wlo + ((size_t)e * D_DIM + n0) * D_DIM;

    float acc[2][4][4];
    #pragma unroll
    for (int mt = 0; mt < 2; mt++)
        #pragma unroll
        for (int nt = 0; nt < 4; nt++)
            #pragma unroll
            for (int c = 0; c < 4; c++) acc[mt][nt][c] = 0.0f;

    load_stage(sbuf3[0], stok, wh, wl, 0, tid);
    CP_COMMIT();
    load_stage(sbuf3[1], stok, wh, wl, BKh, tid);
    CP_COMMIT();

    const int lrow = lane & 15;
    const int lsel = lane >> 4;

    int sidx = 0;
    int pidx = 2;
    for (int c = 0; c < NCHUNK; c++) {
        if (c == NCHUNK - 1) { CP_WAIT0(); } else { CP_WAIT1(); }
        __syncthreads();
        if (c + 2 < NCHUNK) {
            load_stage(sbuf3[pidx], stok, wh, wl, (c + 2) * BKh, tid);
            CP_COMMIT();
        }

        const uint32_t sbuf = sbuf3[sidx];
        #pragma unroll
        for (int ks = 0; ks < 4; ks++) {
            const int chunk = ks * 2 + lsel;
            uint32_t ahi[2][4];
            #pragma unroll
            for (int mt = 0; mt < 2; mt++) {
                int r = wm + mt * 16 + lrow;
                LDSM4(ahi[mt], sbuf + SWZ(r, chunk));
            }
            uint32_t bhi[2][4], blo[2][4];
            #pragma unroll
            for (int ng = 0; ng < 2; ng++) {
                int r = wn + ng * 16 + lrow;
                uint32_t bd = sbuf + OFF_BHI + SWZ(r, chunk);
                LDSM4(bhi[ng], bd);
                LDSM4(blo[ng], bd + 16384);
            }
            #pragma unroll
            for (int mt = 0; mt < 2; mt++)
                #pragma unroll
                for (int nt = 0; nt < 4; nt++) {
                    int ng = nt >> 1, o = nt & 1;
                    MMA16816(acc[mt][nt], ahi[mt], bhi[ng][o], bhi[ng][2 + o]);
                    MMA16816(acc[mt][nt], ahi[mt], blo[ng][o], blo[ng][2 + o]);
                }
        }

        sidx = (sidx + 1 == NSTAGE) ? 0 : sidx + 1;
        pidx = (pidx + 1 == NSTAGE) ? 0 : pidx + 1;
    }

    // epilogue: fused bias + exp, scatter to per-slot partials
    #pragma unroll
    for (int mt = 0; mt < 2; mt++) {
        #pragma unroll
        for (int h = 0; h < 2; h++) {
            int m = wm + mt * 16 + (lane >> 2) + h * 8;
            int slot = sslot[m];
            if (slot < 0) continue;
            float* pr = g_partial + ((size_t)slot << 10);
            #pragma unroll
            for (int nt = 0; nt < 4; nt++) {
                int col = n0 + wn + nt * 8 + (lane & 3) * 2;
                float2 bv = *(const float2*)(bias + (size_t)e * D_DIM + col);
                float2 o;
                o.x = expf(acc[mt][nt][h * 2 + 0] + bv.x);
                o.y = expf(acc[mt][nt][h * 2 + 1] + bv.y);
                *(float2*)(pr + col) = o;
            }
        }
    }
}

// ---------------- kernel 4: combine ----------------
__global__ void combine_kernel(float* __restrict__ out) {
    int idx = blockIdx.x * 256 + threadIdx.x;
    int b = idx >> 8;
    int h4 = (idx & 255) << 2;
    float g0 = g_gate[b * 2 + 0];
    float g1 = g_gate[b * 2 + 1];
    float4 p0 = *(const float4*)(g_partial + ((size_t)(b * 2 + 0) << 10) + h4);
    float4 p1 = *(const float4*)(g_partial + ((size_t)(b * 2 + 1) << 10) + h4);
    float4 o;
    float c0 = fmaf(g0, p0.x, g1 * p1.x);
    float c1 = fmaf(g0, p0.y, g1 * p1.y);
    float c2 = fmaf(g0, p0.z, g1 * p1.z);
    float c3 = fmaf(g0, p0.w, g1 * p1.w);
    const float EPSF = 2.2204460492503131e-16f;
    o.x = logf(c0 == 0.0f ? EPSF : c0);
    o.y = logf(c1 == 0.0f ? EPSF : c1);
    o.z = logf(c2 == 0.0f ? EPSF : c2);
    o.w = logf(c3 == 0.0f ? EPSF : c3);
    *(float4*)(out + (size_t)b * D_DIM + h4) = o;
}

// ---------------- launch ----------------
extern "C" void kernel_launch(void* const* d_in, const int* in_sizes, int n_in,
                              void* d_out, int out_size) {
    const float* x         = (const float*)d_in[0];
    const float* noise     = (const float*)d_in[1];
    const float* w_gate    = (const float*)d_in[2];
    const float* w_noise   = (const float*)d_in[3];
    const float* W_experts = (const float*)d_in[4];
    const float* b_experts = (const float*)d_in[5];
    float* out = (float*)d_out;

    cudaFuncSetAttribute(expert_hmma_kernel,
                         cudaFuncAttributeMaxDynamicSharedMemorySize, SMEM_GEMM);

    zero_counts_kernel<<<1, 32>>>();
    gating_kernel<<<B_TOK / 8, 256>>>(x, noise, w_gate, w_noise);

    dim3 pgrid(D_DIM / 32, D_DIM / 32, E_NUM);
    prep_w_kernel<<<pgrid, dim3(32, 8, 1)>>>(W_experts);

    dim3 ggrid(D_DIM / BNh, B_TOK / BMh, E_NUM);  // (8, 64, 8)
    expert_hmma_kernel<<<ggrid, NTHR, SMEM_GEMM>>>(b_experts);

    combine_kernel<<<(B_TOK * D_DIM / 4) / 256, 256>>>(out);
}

// round 7
// speedup vs baseline: 1.2692x; 1.0090x over previous
#include <cuda_runtime.h>
#include <cuda_fp16.h>
#include <math.h>
#include <stdint.h>

#define B_TOK 8192
#define D_DIM 1024
#define E_NUM 8

// ---------------- scratch (device globals; no allocs allowed) ----------------
__device__ int    g_counts[E_NUM];
__device__ int    g_bucket_tok [E_NUM * B_TOK];
__device__ int    g_bucket_slot[E_NUM * B_TOK];
__device__ float  g_gate[B_TOK * 2];
__device__ float  g_partial[(size_t)B_TOK * 2 * D_DIM];       // exp(expert_out) per slot
__device__ __half g_xhi[(size_t)B_TOK * D_DIM];
__device__ __half g_whi[(size_t)E_NUM * D_DIM * D_DIM];       // W^T hi, [E][N][K]
__device__ __half g_wlo[(size_t)E_NUM * D_DIM * D_DIM];       // W^T lo, [E][N][K]

// ---------------- PTX helpers (sm_80-baseline only) ----------------
__device__ __forceinline__ uint32_t smem_u32(const void* p) {
    uint32_t a;
    asm("{ .reg .u64 t; cvta.to.shared.u64 t, %1; cvt.u32.u64 %0, t; }" : "=r"(a) : "l"(p));
    return a;
}

#define CP16(dst, src) \
    asm volatile("cp.async.cg.shared.global [%0], [%1], 16;" \
        :: "r"(dst), "l"(__cvta_generic_to_global(src)) : "memory")
#define CP_COMMIT() asm volatile("cp.async.commit_group;" ::: "memory")
#define CP_WAIT1()  asm volatile("cp.async.wait_group 1;" ::: "memory")
#define CP_WAIT0()  asm volatile("cp.async.wait_group 0;" ::: "memory")

#define LDSM4(r, addr) \
    asm volatile("ldmatrix.sync.aligned.m8n8.x4.shared.b16 {%0,%1,%2,%3}, [%4];" \
        : "=r"((r)[0]), "=r"((r)[1]), "=r"((r)[2]), "=r"((r)[3]) : "r"(addr))

#define MMA16816(d, a, b0, b1) \
    asm volatile("mma.sync.aligned.m16n8k16.row.col.f32.f16.f16.f32 " \
        "{%0,%1,%2,%3}, {%4,%5,%6,%7}, {%8,%9}, {%0,%1,%2,%3};" \
        : "+f"((d)[0]), "+f"((d)[1]), "+f"((d)[2]), "+f"((d)[3]) \
        : "r"((a)[0]), "r"((a)[1]), "r"((a)[2]), "r"((a)[3]), "r"(b0), "r"(b1))

#define SWZ(row, chunk) ((uint32_t)((row) * 128 + (((chunk) ^ ((row) & 7)) << 4)))

// ---------------- kernel 0: zero bucket counts ----------------
__global__ void zero_counts_kernel() {
    if (threadIdx.x < E_NUM) g_counts[threadIdx.x] = 0;
}

__device__ __forceinline__ float softplus_stable(float z) {
    return fmaxf(z, 0.0f) + log1pf(expf(-fabsf(z)));
}

// ---------------- kernel 1: FUSED gating + x-split + W transpose/split ----------
// blocks [0, 1024):          gating for 8 tokens each (8 warps)
// blocks [1024, 1024+8192):  prep_w 32x32 transpose tiles
#define GATE_BLKS (B_TOK / 8)

__device__ void gating_block(const float* __restrict__ x,
                             const float* __restrict__ noise,
                             const float* __restrict__ w_gate,
                             const float* __restrict__ w_noise,
                             int bx) {
    const int warp = threadIdx.x >> 5;
    const int lane = threadIdx.x & 31;
    const int b = bx * 8 + warp;

    float accC[8] = {0.f,0.f,0.f,0.f,0.f,0.f,0.f,0.f};
    float accN[8] = {0.f,0.f,0.f,0.f,0.f,0.f,0.f,0.f};
    const float* xr = x + (size_t)b * D_DIM;
    __half2* xh = (__half2*)(g_xhi + (size_t)b * D_DIM);

    #pragma unroll
    for (int i = 0; i < 16; i++) {
        int d = 2 * lane + 64 * i;
        float2 v = *(const float2*)(xr + d);

        xh[d >> 1] = __halves2half2(__float2half_rn(v.x), __float2half_rn(v.y));

        const float4* wg0 = reinterpret_cast<const float4*>(w_gate  + (size_t)d * 8);
        const float4* wn0 = reinterpret_cast<const float4*>(w_noise + (size_t)d * 8);
        float4 ga = wg0[0], gb = wg0[1], gc = wg0[2], gd = wg0[3];
        float4 na = wn0[0], nb = wn0[1], nc = wn0[2], nd = wn0[3];
        accC[0] = fmaf(v.x, ga.x, accC[0]); accC[1] = fmaf(v.x, ga.y, accC[1]);
        accC[2] = fmaf(v.x, ga.z, accC[2]); accC[3] = fmaf(v.x, ga.w, accC[3]);
        accC[4] = fmaf(v.x, gb.x, accC[4]); accC[5] = fmaf(v.x, gb.y, accC[5]);
        accC[6] = fmaf(v.x, gb.z, accC[6]); accC[7] = fmaf(v.x, gb.w, accC[7]);
        accC[0] = fmaf(v.y, gc.x, accC[0]); accC[1] = fmaf(v.y, gc.y, accC[1]);
        accC[2] = fmaf(v.y, gc.z, accC[2]); accC[3] = fmaf(v.y, gc.w, accC[3]);
        accC[4] = fmaf(v.y, gd.x, accC[4]); accC[5] = fmaf(v.y, gd.y, accC[5]);
        accC[6] = fmaf(v.y, gd.z, accC[6]); accC[7] = fmaf(v.y, gd.w, accC[7]);
        accN[0] = fmaf(v.x, na.x, accN[0]); accN[1] = fmaf(v.x, na.y, accN[1]);
        accN[2] = fmaf(v.x, na.z, accN[2]); accN[3] = fmaf(v.x, na.w, accN[3]);
        accN[4] = fmaf(v.x, nb.x, accN[4]); accN[5] = fmaf(v.x, nb.y, accN[5]);
        accN[6] = fmaf(v.x, nb.z, accN[6]); accN[7] = fmaf(v.x, nb.w, accN[7]);
        accN[0] = fmaf(v.y, nc.x, accN[0]); accN[1] = fmaf(v.y, nc.y, accN[1]);
        accN[2] = fmaf(v.y, nc.z, accN[2]); accN[3] = fmaf(v.y, nc.w, accN[3]);
        accN[4] = fmaf(v.y, nd.x, accN[4]); accN[5] = fmaf(v.y, nd.y, accN[5]);
        accN[6] = fmaf(v.y, nd.z, accN[6]); accN[7] = fmaf(v.y, nd.w, accN[7]);
    }

    #pragma unroll
    for (int e = 0; e < 8; e++) {
        #pragma unroll
        for (int off = 16; off > 0; off >>= 1) {
            accC[e] += __shfl_xor_sync(0xffffffffu, accC[e], off);
            accN[e] += __shfl_xor_sync(0xffffffffu, accN[e], off);
        }
    }

    if (lane == 0) {
        float logits[8];
        #pragma unroll
        for (int e = 0; e < 8; e++) {
            float sd = softplus_stable(accN[e]) + 0.01f;
            logits[e] = fmaf(noise[(size_t)b * E_NUM + e], sd, accC[e]);
        }
        int i0 = 0; float v0 = logits[0];
        #pragma unroll
        for (int e = 1; e < 8; e++) { if (logits[e] > v0) { v0 = logits[e]; i0 = e; } }
        int i1 = -1; float v1 = -INFINITY;
        #pragma unroll
        for (int e = 0; e < 8; e++) {
            if (e != i0 && logits[e] > v1) { v1 = logits[e]; i1 = e; }
        }
        float ex = expf(v1 - v0);
        float inv = 1.0f / (1.0f + ex);
        g_gate[b * 2 + 0] = inv;
        g_gate[b * 2 + 1] = ex * inv;

        int p0 = atomicAdd(&g_counts[i0], 1);
        g_bucket_tok [i0 * B_TOK + p0] = b;
        g_bucket_slot[i0 * B_TOK + p0] = b * 2 + 0;
        int p1 = atomicAdd(&g_counts[i1], 1);
        g_bucket_tok [i1 * B_TOK + p1] = b;
        g_bucket_slot[i1 * B_TOK + p1] = b * 2 + 1;
    }
}

__device__ void prep_w_block(const float* __restrict__ W, int t) {
    __shared__ float tile[32][33];
    const int e   = t >> 10;           // 1024 tiles per expert
    const int rem = t & 1023;
    const int k0  = (rem >> 5) * 32;
    const int n0  = (rem & 31) * 32;
    const int tx  = threadIdx.x & 31;
    const int ty  = threadIdx.x >> 5;  // 0..7
    const float* We = W + (size_t)e * D_DIM * D_DIM;

    #pragma unroll
    for (int i = 0; i < 32; i += 8)
        tile[ty + i][tx] = We[(size_t)(k0 + ty + i) * D_DIM + n0 + tx];
    __syncthreads();

    #pragma unroll
    for (int i = 0; i < 32; i += 8) {
        float v = tile[tx][ty + i];
        __half hi = __float2half_rn(v);
        __half lo = __float2half_rn(v - __half2float(hi));
        size_t o = ((size_t)(e * D_DIM + n0 + ty + i)) * D_DIM + k0 + tx;
        g_whi[o] = hi;
        g_wlo[o] = lo;
    }
}

__global__ __launch_bounds__(256)
void prep_fused_kernel(const float* __restrict__ x,
                       const float* __restrict__ noise,
                       const float* __restrict__ w_gate,
                       const float* __restrict__ w_noise,
                       const float* __restrict__ W) {
    const int bx = blockIdx.x;
    if (bx < GATE_BLKS) gating_block(x, noise, w_gate, w_noise, bx);
    else                prep_w_block(W, bx - GATE_BLKS);
}

// ---------------- kernel 2: routed 2-pass fp16 mma.sync GEMM (256x128 tile) ----
#define BMh 256
#define BNh 128
#define BKh 64
#define NCHUNK (D_DIM / BKh)           // 16
#define STG 65536                      // Ahi 32K | Bhi 16K | Blo 16K
#define OFF_BHI 32768
#define OFF_BLO 49152
#define NSTAGE 3
#define NTHR 512
#define SMEM_GEMM (2048 + NSTAGE * STG)

__device__ __forceinline__ void load_stage(uint32_t sbuf, const int* stok,
                                           const __half* __restrict__ wh,
                                           const __half* __restrict__ wl,
                                           int kt, int tid) {
    #pragma unroll
    for (int i = 0; i < 4; i++) {              // A: 256 rows x 8 chunks
        int lin = i * NTHR + tid;
        int row = lin >> 3, ch = lin & 7;
        int tok = stok[row];
        const __half* sa = g_xhi + (size_t)tok * D_DIM + kt + ch * 8;
        CP16(sbuf + SWZ(row, ch), sa);
    }
    #pragma unroll
    for (int i = 0; i < 2; i++) {              // B: 128 rows x 8 chunks, hi+lo
        int lin = i * NTHR + tid;
        int row = lin >> 3, ch = lin & 7;
        const __half* sb = wh + (size_t)row * D_DIM + kt + ch * 8;
        const __half* sl = wl + (size_t)row * D_DIM + kt + ch * 8;
        uint32_t d = sbuf + OFF_BHI + SWZ(row, ch);
        CP16(d, sb);
        CP16(d + 16384, sl);                   // OFF_BLO - OFF_BHI
    }
}

__global__ __launch_bounds__(NTHR, 1)
void expert_hmma_kernel(const float* __restrict__ bias) {
    const int e     = blockIdx.z;
    const int count = g_counts[e];
    const int m0    = blockIdx.y * BMh;
    if (m0 >= count) return;
    const int n0    = blockIdx.x * BNh;

    extern __shared__ char smraw[];
    int* stok  = (int*)smraw;            // [256]
    int* sslot = (int*)(smraw + 1024);   // [256]
    const uint32_t sbase = smem_u32(smraw) + 2048;
    uint32_t sbuf3[NSTAGE];
    #pragma unroll
    for (int s = 0; s < NSTAGE; s++) sbuf3[s] = sbase + s * STG;

    const int tid  = threadIdx.x;
    const int wid  = tid >> 5;
    const int lane = tid & 31;
    const int wm   = (wid & 7) * 32;     // 8 warps over 256 m
    const int wn   = (wid >> 3) * 64;    // 2 warps over 128 n

    if (tid < BMh) {
        int m = m0 + tid;
        bool ok = (m < count);
        stok [tid] = ok ? g_bucket_tok [e * B_TOK + m] : 0;
        sslot[tid] = ok ? g_bucket_slot[e * B_TOK + m] : -1;
    }
    __syncthreads();

    const __half* wh = g_whi + ((size_t)e * D_DIM + n0) * D_DIM;
    const __half* wl = g_wlo + ((size_t)e * D_DIM + n0) * D_DIM;

    float acc[2][8][4];
    #pragma unroll
    for (int mt = 0; mt < 2; mt++)
        #pragma unroll
        for (int nt = 0; nt < 8; nt++)
            #pragma unroll
            for (int c = 0; c < 4; c++) acc[mt][nt][c] = 0.0f;

    load_stage(sbuf3[0], stok, wh, wl, 0, tid);
    CP_COMMIT();
    load_stage(sbuf3[1], stok, wh, wl, BKh, tid);
    CP_COMMIT();

    const int lrow = lane & 15;
    const int lsel = lane >> 4;

    int sidx = 0;
    int pidx = 2;
    for (int c = 0; c < NCHUNK; c++) {
        if (c == NCHUNK - 1) { CP_WAIT0(); } else { CP_WAIT1(); }
        __syncthreads();
        if (c + 2 < NCHUNK) {
            load_stage(sbuf3[pidx], stok, wh, wl, (c + 2) * BKh, tid);
            CP_COMMIT();
        }

        const uint32_t sbuf = sbuf3[sidx];
        #pragma unroll
        for (int ks = 0; ks < 4; ks++) {
            const int chunk = ks * 2 + lsel;
            uint32_t ahi[2][4];
            #pragma unroll
            for (int mt = 0; mt < 2; mt++) {
                int r = wm + mt * 16 + lrow;
                LDSM4(ahi[mt], sbuf + SWZ(r, chunk));
            }
            #pragma unroll
            for (int ng = 0; ng < 4; ng++) {           // 4 n16-groups over wn..wn+63
                int r = wn + ng * 16 + lrow;
                uint32_t bd = sbuf + OFF_BHI + SWZ(r, chunk);
                uint32_t bhi[4], blo[4];
                LDSM4(bhi, bd);
                LDSM4(blo, bd + 16384);
                #pragma unroll
                for (int mt = 0; mt < 2; mt++) {
                    #pragma unroll
                    for (int o = 0; o < 2; o++) {
                        MMA16816(acc[mt][ng * 2 + o], ahi[mt], bhi[o], bhi[2 + o]);
                        MMA16816(acc[mt][ng * 2 + o], ahi[mt], blo[o], blo[2 + o]);
                    }
                }
            }
        }

        sidx = (sidx + 1 == NSTAGE) ? 0 : sidx + 1;
        pidx = (pidx + 1 == NSTAGE) ? 0 : pidx + 1;
    }

    // epilogue: fused bias + exp, scatter to per-slot partials
    #pragma unroll
    for (int mt = 0; mt < 2; mt++) {
        #pragma unroll
        for (int h = 0; h < 2; h++) {
            int m = wm + mt * 16 + (lane >> 2) + h * 8;
            int slot = sslot[m];
            if (slot < 0) continue;
            float* pr = g_partial + ((size_t)slot << 10);
            #pragma unroll
            for (int nt = 0; nt < 8; nt++) {
                int col = n0 + wn + nt * 8 + (lane & 3) * 2;
                float2 bv = *(const float2*)(bias + (size_t)e * D_DIM + col);
                float2 o;
                o.x = expf(acc[mt][nt][h * 2 + 0] + bv.x);
                o.y = expf(acc[mt][nt][h * 2 + 1] + bv.y);
                *(float2*)(pr + col) = o;
            }
        }
    }
}

// ---------------- kernel 3: combine ----------------
__global__ void combine_kernel(float* __restrict__ out) {
    int idx = blockIdx.x * 256 + threadIdx.x;
    int b = idx >> 8;
    int h4 = (idx & 255) << 2;
    float g0 = g_gate[b * 2 + 0];
    float g1 = g_gate[b * 2 + 1];
    float4 p0 = *(const float4*)(g_partial + ((size_t)(b * 2 + 0) << 10) + h4);
    float4 p1 = *(const float4*)(g_partial + ((size_t)(b * 2 + 1) << 10) + h4);
    float4 o;
    float c0 = fmaf(g0, p0.x, g1 * p1.x);
    float c1 = fmaf(g0, p0.y, g1 * p1.y);
    float c2 = fmaf(g0, p0.z, g1 * p1.z);
    float c3 = fmaf(g0, p0.w, g1 * p1.w);
    const float EPSF = 2.2204460492503131e-16f;
    o.x = logf(c0 == 0.0f ? EPSF : c0);
    o.y = logf(c1 == 0.0f ? EPSF : c1);
    o.z = logf(c2 == 0.0f ? EPSF : c2);
    o.w = logf(c3 == 0.0f ? EPSF : c3);
    *(float4*)(out + (size_t)b * D_DIM + h4) = o;
}

// ---------------- launch ----------------
extern "C" void kernel_launch(void* const* d_in, const int* in_sizes, int n_in,
                              void* d_out, int out_size) {
    const float* x         = (const float*)d_in[0];
    const float* noise     = (const float*)d_in[1];
    const float* w_gate    = (const float*)d_in[2];
    const float* w_noise   = (const float*)d_in[3];
    const float* W_experts = (const float*)d_in[4];
    const float* b_experts = (const float*)d_in[5];
    float* out = (float*)d_out;

    cudaFuncSetAttribute(expert_hmma_kernel,
                         cudaFuncAttributeMaxDynamicSharedMemorySize, SMEM_GEMM);

    zero_counts_kernel<<<1, 32>>>();
    prep_fused_kernel<<<GATE_BLKS + 8192, 256>>>(x, noise, w_gate, w_noise, W_experts);

    dim3 ggrid(D_DIM / BNh, B_TOK / BMh, E_NUM);  // (8, 32, 8)
    expert_hmma_kernel<<<ggrid, NTHR, SMEM_GEMM>>>(b_experts);

    combine_kernel<<<(B_TOK * D_DIM / 4) / 256, 256>>>(out);
}

// round 8
// speedup vs baseline: 1.7706x; 1.3951x over previous
#include <cuda_runtime.h>
#include <cuda_fp16.h>
#include <math.h>
#include <stdint.h>

#define B_TOK 8192
#define D_DIM 1024
#define E_NUM 8

// ---------------- scratch (device globals; no allocs allowed) ----------------
__device__ int    g_counts[E_NUM];
__device__ int    g_bucket_tok [E_NUM * B_TOK];
__device__ int    g_bucket_slot[E_NUM * B_TOK];
__device__ float  g_gate[B_TOK * 2];
__device__ float  g_partial[(size_t)B_TOK * 2 * D_DIM];       // exp(expert_out) per slot
__device__ __half g_xhi[(size_t)B_TOK * D_DIM];
__device__ __half g_whi[(size_t)E_NUM * D_DIM * D_DIM];       // W^T fp16, [E][N][K]

// ---------------- PTX helpers (sm_80-baseline only) ----------------
__device__ __forceinline__ uint32_t smem_u32(const void* p) {
    uint32_t a;
    asm("{ .reg .u64 t; cvta.to.shared.u64 t, %1; cvt.u32.u64 %0, t; }" : "=r"(a) : "l"(p));
    return a;
}

#define CP16(dst, src) \
    asm volatile("cp.async.cg.shared.global [%0], [%1], 16;" \
        :: "r"(dst), "l"(__cvta_generic_to_global(src)) : "memory")
#define CP_COMMIT() asm volatile("cp.async.commit_group;" ::: "memory")
#define CP_WAIT1()  asm volatile("cp.async.wait_group 1;" ::: "memory")
#define CP_WAIT0()  asm volatile("cp.async.wait_group 0;" ::: "memory")

#define LDSM4(r, addr) \
    asm volatile("ldmatrix.sync.aligned.m8n8.x4.shared.b16 {%0,%1,%2,%3}, [%4];" \
        : "=r"((r)[0]), "=r"((r)[1]), "=r"((r)[2]), "=r"((r)[3]) : "r"(addr))

#define MMA16816(d, a, b0, b1) \
    asm volatile("mma.sync.aligned.m16n8k16.row.col.f32.f16.f16.f32 " \
        "{%0,%1,%2,%3}, {%4,%5,%6,%7}, {%8,%9}, {%0,%1,%2,%3};" \
        : "+f"((d)[0]), "+f"((d)[1]), "+f"((d)[2]), "+f"((d)[3]) \
        : "r"((a)[0]), "r"((a)[1]), "r"((a)[2]), "r"((a)[3]), "r"(b0), "r"(b1))

#define SWZ(row, chunk) ((uint32_t)((row) * 128 + (((chunk) ^ ((row) & 7)) << 4)))

// ---------------- kernel 0: zero bucket counts ----------------
__global__ void zero_counts_kernel() {
    if (threadIdx.x < E_NUM) g_counts[threadIdx.x] = 0;
}

__device__ __forceinline__ float softplus_stable(float z) {
    return fmaxf(z, 0.0f) + log1pf(expf(-fabsf(z)));
}

// ---------------- kernel 1: FUSED gating + x-split + W transpose/cast ----------
#define GATE_BLKS (B_TOK / 8)

__device__ void gating_block(const float* __restrict__ x,
                             const float* __restrict__ noise,
                             const float* __restrict__ w_gate,
                             const float* __restrict__ w_noise,
                             int bx) {
    const int warp = threadIdx.x >> 5;
    const int lane = threadIdx.x & 31;
    const int b = bx * 8 + warp;

    float accC[8] = {0.f,0.f,0.f,0.f,0.f,0.f,0.f,0.f};
    float accN[8] = {0.f,0.f,0.f,0.f,0.f,0.f,0.f,0.f};
    const float* xr = x + (size_t)b * D_DIM;
    __half2* xh = (__half2*)(g_xhi + (size_t)b * D_DIM);

    #pragma unroll
    for (int i = 0; i < 16; i++) {
        int d = 2 * lane + 64 * i;
        float2 v = *(const float2*)(xr + d);

        xh[d >> 1] = __halves2half2(__float2half_rn(v.x), __float2half_rn(v.y));

        const float4* wg0 = reinterpret_cast<const float4*>(w_gate  + (size_t)d * 8);
        const float4* wn0 = reinterpret_cast<const float4*>(w_noise + (size_t)d * 8);
        float4 ga = wg0[0], gb = wg0[1], gc = wg0[2], gd = wg0[3];
        float4 na = wn0[0], nb = wn0[1], nc = wn0[2], nd = wn0[3];
        accC[0] = fmaf(v.x, ga.x, accC[0]); accC[1] = fmaf(v.x, ga.y, accC[1]);
        accC[2] = fmaf(v.x, ga.z, accC[2]); accC[3] = fmaf(v.x, ga.w, accC[3]);
        accC[4] = fmaf(v.x, gb.x, accC[4]); accC[5] = fmaf(v.x, gb.y, accC[5]);
        accC[6] = fmaf(v.x, gb.z, accC[6]); accC[7] = fmaf(v.x, gb.w, accC[7]);
        accC[0] = fmaf(v.y, gc.x, accC[0]); accC[1] = fmaf(v.y, gc.y, accC[1]);
        accC[2] = fmaf(v.y, gc.z, accC[2]); accC[3] = fmaf(v.y, gc.w, accC[3]);
        accC[4] = fmaf(v.y, gd.x, accC[4]); accC[5] = fmaf(v.y, gd.y, accC[5]);
        accC[6] = fmaf(v.y, gd.z, accC[6]); accC[7] = fmaf(v.y, gd.w, accC[7]);
        accN[0] = fmaf(v.x, na.x, accN[0]); accN[1] = fmaf(v.x, na.y, accN[1]);
        accN[2] = fmaf(v.x, na.z, accN[2]); accN[3] = fmaf(v.x, na.w, accN[3]);
        accN[4] = fmaf(v.x, nb.x, accN[4]); accN[5] = fmaf(v.x, nb.y, accN[5]);
        accN[6] = fmaf(v.x, nb.z, accN[6]); accN[7] = fmaf(v.x, nb.w, accN[7]);
        accN[0] = fmaf(v.y, nc.x, accN[0]); accN[1] = fmaf(v.y, nc.y, accN[1]);
        accN[2] = fmaf(v.y, nc.z, accN[2]); accN[3] = fmaf(v.y, nc.w, accN[3]);
        accN[4] = fmaf(v.y, nd.x, accN[4]); accN[5] = fmaf(v.y, nd.y, accN[5]);
        accN[6] = fmaf(v.y, nd.z, accN[6]); accN[7] = fmaf(v.y, nd.w, accN[7]);
    }

    #pragma unroll
    for (int e = 0; e < 8; e++) {
        #pragma unroll
        for (int off = 16; off > 0; off >>= 1) {
            accC[e] += __shfl_xor_sync(0xffffffffu, accC[e], off);
            accN[e] += __shfl_xor_sync(0xffffffffu, accN[e], off);
        }
    }

    if (lane == 0) {
        float logits[8];
        #pragma unroll
        for (int e = 0; e < 8; e++) {
            float sd = softplus_stable(accN[e]) + 0.01f;
            logits[e] = fmaf(noise[(size_t)b * E_NUM + e], sd, accC[e]);
        }
        int i0 = 0; float v0 = logits[0];
        #pragma unroll
        for (int e = 1; e < 8; e++) { if (logits[e] > v0) { v0 = logits[e]; i0 = e; } }
        int i1 = -1; float v1 = -INFINITY;
        #pragma unroll
        for (int e = 0; e < 8; e++) {
            if (e != i0 && logits[e] > v1) { v1 = logits[e]; i1 = e; }
        }
        float ex = expf(v1 - v0);
        float inv = 1.0f / (1.0f + ex);
        g_gate[b * 2 + 0] = inv;
        g_gate[b * 2 + 1] = ex * inv;

        int p0 = atomicAdd(&g_counts[i0], 1);
        g_bucket_tok [i0 * B_TOK + p0] = b;
        g_bucket_slot[i0 * B_TOK + p0] = b * 2 + 0;
        int p1 = atomicAdd(&g_counts[i1], 1);
        g_bucket_tok [i1 * B_TOK + p1] = b;
        g_bucket_slot[i1 * B_TOK + p1] = b * 2 + 1;
    }
}

__device__ void prep_w_block(const float* __restrict__ W, int t) {
    __shared__ float tile[32][33];
    const int e   = t >> 10;
    const int rem = t & 1023;
    const int k0  = (rem >> 5) * 32;
    const int n0  = (rem & 31) * 32;
    const int tx  = threadIdx.x & 31;
    const int ty  = threadIdx.x >> 5;  // 0..7
    const float* We = W + (size_t)e * D_DIM * D_DIM;

    #pragma unroll
    for (int i = 0; i < 32; i += 8)
        tile[ty + i][tx] = We[(size_t)(k0 + ty + i) * D_DIM + n0 + tx];
    __syncthreads();

    #pragma unroll
    for (int i = 0; i < 32; i += 8) {
        float v = tile[tx][ty + i];
        size_t o = ((size_t)(e * D_DIM + n0 + ty + i)) * D_DIM + k0 + tx;
        g_whi[o] = __float2half_rn(v);
    }
}

__global__ __launch_bounds__(256)
void prep_fused_kernel(const float* __restrict__ x,
                       const float* __restrict__ noise,
                       const float* __restrict__ w_gate,
                       const float* __restrict__ w_noise,
                       const float* __restrict__ W) {
    const int bx = blockIdx.x;
    if (bx < GATE_BLKS) gating_block(x, noise, w_gate, w_noise, bx);
    else                prep_w_block(W, bx - GATE_BLKS);
}

// ---------------- kernel 2: routed 1-pass fp16 mma.sync GEMM (256x128 tile) ----
#define BMh 256
#define BNh 128
#define BKh 64
#define NCHUNK (D_DIM / BKh)           // 16
#define STG 49152                      // A 32K | B 16K
#define OFF_B 32768
#define NSTAGE 3
#define NTHR 512
#define SMEM_GEMM (2048 + NSTAGE * STG)

__device__ __forceinline__ void load_stage(uint32_t sbuf, const int* stok,
                                           const __half* __restrict__ wh,
                                           int kt, int tid) {
    #pragma unroll
    for (int i = 0; i < 4; i++) {              // A: 256 rows x 8 chunks
        int lin = i * NTHR + tid;
        int row = lin >> 3, ch = lin & 7;
        int tok = stok[row];
        const __half* sa = g_xhi + (size_t)tok * D_DIM + kt + ch * 8;
        CP16(sbuf + SWZ(row, ch), sa);
    }
    #pragma unroll
    for (int i = 0; i < 2; i++) {              // B: 128 rows x 8 chunks
        int lin = i * NTHR + tid;
        int row = lin >> 3, ch = lin & 7;
        const __half* sb = wh + (size_t)row * D_DIM + kt + ch * 8;
        CP16(sbuf + OFF_B + SWZ(row, ch), sb);
    }
}

__global__ __launch_bounds__(NTHR, 1)
void expert_hmma_kernel(const float* __restrict__ bias) {
    const int e     = blockIdx.z;
    const int count = g_counts[e];
    const int m0    = blockIdx.y * BMh;
    if (m0 >= count) return;
    const int n0    = blockIdx.x * BNh;

    extern __shared__ char smraw[];
    int* stok  = (int*)smraw;            // [256]
    int* sslot = (int*)(smraw + 1024);   // [256]
    const uint32_t sbase = smem_u32(smraw) + 2048;
    uint32_t sbuf3[NSTAGE];
    #pragma unroll
    for (int s = 0; s < NSTAGE; s++) sbuf3[s] = sbase + s * STG;

    const int tid  = threadIdx.x;
    const int wid  = tid >> 5;
    const int lane = tid & 31;
    const int wm   = (wid & 7) * 32;     // 8 warps over 256 m
    const int wn   = (wid >> 3) * 64;    // 2 warps over 128 n

    if (tid < BMh) {
        int m = m0 + tid;
        bool ok = (m < count);
        stok [tid] = ok ? g_bucket_tok [e * B_TOK + m] : 0;
        sslot[tid] = ok ? g_bucket_slot[e * B_TOK + m] : -1;
    }
    __syncthreads();

    const __half* wh = g_whi + ((size_t)e * D_DIM + n0) * D_DIM;

    float acc[2][8][4];
    #pragma unroll
    for (int mt = 0; mt < 2; mt++)
        #pragma unroll
        for (int nt = 0; nt < 8; nt++)
            #pragma unroll
            for (int c = 0; c < 4; c++) acc[mt][nt][c] = 0.0f;

    load_stage(sbuf3[0], stok, wh, 0, tid);
    CP_COMMIT();
    load_stage(sbuf3[1], stok, wh, BKh, tid);
    CP_COMMIT();

    const int lrow = lane & 15;
    const int lsel = lane >> 4;

    int sidx = 0;
    int pidx = 2;
    for (int c = 0; c < NCHUNK; c++) {
        if (c == NCHUNK - 1) { CP_WAIT0(); } else { CP_WAIT1(); }
        __syncthreads();
        if (c + 2 < NCHUNK) {
            load_stage(sbuf3[pidx], stok, wh, (c + 2) * BKh, tid);
            CP_COMMIT();
        }

        const uint32_t sbuf = sbuf3[sidx];
        #pragma unroll
        for (int ks = 0; ks < 4; ks++) {
            const int chunk = ks * 2 + lsel;
            uint32_t ahi[2][4];
            #pragma unroll
            for (int mt = 0; mt < 2; mt++) {
                int r = wm + mt * 16 + lrow;
                LDSM4(ahi[mt], sbuf + SWZ(r, chunk));
            }
            #pragma unroll
            for (int ng = 0; ng < 4; ng++) {           // 4 n16-groups over wn..wn+63
                int r = wn + ng * 16 + lrow;
                uint32_t bhi[4];
                LDSM4(bhi, sbuf + OFF_B + SWZ(r, chunk));
                #pragma unroll
                for (int mt = 0; mt < 2; mt++) {
                    #pragma unroll
                    for (int o = 0; o < 2; o++)
                        MMA16816(acc[mt][ng * 2 + o], ahi[mt], bhi[o], bhi[2 + o]);
                }
            }
        }

        sidx = (sidx + 1 == NSTAGE) ? 0 : sidx + 1;
        pidx = (pidx + 1 == NSTAGE) ? 0 : pidx + 1;
    }

    // epilogue: fused bias + exp, scatter to per-slot partials
    #pragma unroll
    for (int mt = 0; mt < 2; mt++) {
        #pragma unroll
        for (int h = 0; h < 2; h++) {
            int m = wm + mt * 16 + (lane >> 2) + h * 8;
            int slot = sslot[m];
            if (slot < 0) continue;
            float* pr = g_partial + ((size_t)slot << 10);
            #pragma unroll
            for (int nt = 0; nt < 8; nt++) {
                int col = n0 + wn + nt * 8 + (lane & 3) * 2;
                float2 bv = *(const float2*)(bias + (size_t)e * D_DIM + col);
                float2 o;
                o.x = expf(acc[mt][nt][h * 2 + 0] + bv.x);
                o.y = expf(acc[mt][nt][h * 2 + 1] + bv.y);
                *(float2*)(pr + col) = o;
            }
        }
    }
}

// ---------------- kernel 3: combine ----------------
__global__ void combine_kernel(float* __restrict__ out) {
    int idx = blockIdx.x * 256 + threadIdx.x;
    int b = idx >> 8;
    int h4 = (idx & 255) << 2;
    float g0 = g_gate[b * 2 + 0];
    float g1 = g_gate[b * 2 + 1];
    float4 p0 = *(const float4*)(g_partial + ((size_t)(b * 2 + 0) << 10) + h4);
    float4 p1 = *(const float4*)(g_partial + ((size_t)(b * 2 + 1) << 10) + h4);
    float4 o;
    float c0 = fmaf(g0, p0.x, g1 * p1.x);
    float c1 = fmaf(g0, p0.y, g1 * p1.y);
    float c2 = fmaf(g0, p0.z, g1 * p1.z);
    float c3 = fmaf(g0, p0.w, g1 * p1.w);
    const float EPSF = 2.2204460492503131e-16f;
    o.x = logf(c0 == 0.0f ? EPSF : c0);
    o.y = logf(c1 == 0.0f ? EPSF : c1);
    o.z = logf(c2 == 0.0f ? EPSF : c2);
    o.w = logf(c3 == 0.0f ? EPSF : c3);
    *(float4*)(out + (size_t)b * D_DIM + h4) = o;
}

// ---------------- launch ----------------
extern "C" void kernel_launch(void* const* d_in, const int* in_sizes, int n_in,
                              void* d_out, int out_size) {
    const float* x         = (const float*)d_in[0];
    const float* noise     = (const float*)d_in[1];
    const float* w_gate    = (const float*)d_in[2];
    const float* w_noise   = (const float*)d_in[3];
    const float* W_experts = (const float*)d_in[4];
    const float* b_experts = (const float*)d_in[5];
    float* out = (float*)d_out;

    cudaFuncSetAttribute(expert_hmma_kernel,
                         cudaFuncAttributeMaxDynamicSharedMemorySize, SMEM_GEMM);

    zero_counts_kernel<<<1, 32>>>();
    prep_fused_kernel<<<GATE_BLKS + 8192, 256>>>(x, noise, w_gate, w_noise, W_experts);

    dim3 ggrid(D_DIM / BNh, B_TOK / BMh, E_NUM);  // (8, 32, 8)
    expert_hmma_kernel<<<ggrid, NTHR, SMEM_GEMM>>>(b_experts);

    combine_kernel<<<(B_TOK * D_DIM / 4) / 256, 256>>>(out);
}

// round 9
// speedup vs baseline: 1.9915x; 1.1248x over previous
#include <cuda_runtime.h>
#include <cuda_fp16.h>
#include <math.h>
#include <stdint.h>

#define B_TOK 8192
#define D_DIM 1024
#define E_NUM 8

// ---------------- scratch (device globals; no allocs allowed) ----------------
__device__ int    g_counts[E_NUM];
__device__ int    g_bucket_tok [E_NUM * B_TOK];
__device__ int    g_bucket_slot[E_NUM * B_TOK];
__device__ float  g_gate[B_TOK * 2];
__device__ float  g_partial[(size_t)B_TOK * 2 * D_DIM];       // exp(expert_out) per slot
__device__ __half g_xhi[(size_t)B_TOK * D_DIM];
__device__ __half g_whi[(size_t)E_NUM * D_DIM * D_DIM];       // W^T fp16, [E][N][K]

// ---------------- PTX helpers (sm_80-baseline only) ----------------
__device__ __forceinline__ uint32_t smem_u32(const void* p) {
    uint32_t a;
    asm("{ .reg .u64 t; cvta.to.shared.u64 t, %1; cvt.u32.u64 %0, t; }" : "=r"(a) : "l"(p));
    return a;
}

#define CP16(dst, src) \
    asm volatile("cp.async.cg.shared.global [%0], [%1], 16;" \
        :: "r"(dst), "l"(__cvta_generic_to_global(src)) : "memory")
#define CP_COMMIT() asm volatile("cp.async.commit_group;" ::: "memory")
#define CP_WAIT1()  asm volatile("cp.async.wait_group 1;" ::: "memory")
#define CP_WAIT0()  asm volatile("cp.async.wait_group 0;" ::: "memory")

#define LDSM4(r, addr) \
    asm volatile("ldmatrix.sync.aligned.m8n8.x4.shared.b16 {%0,%1,%2,%3}, [%4];" \
        : "=r"((r)[0]), "=r"((r)[1]), "=r"((r)[2]), "=r"((r)[3]) : "r"(addr))

#define MMA16816(d, a, b0, b1) \
    asm volatile("mma.sync.aligned.m16n8k16.row.col.f32.f16.f16.f32 " \
        "{%0,%1,%2,%3}, {%4,%5,%6,%7}, {%8,%9}, {%0,%1,%2,%3};" \
        : "+f"((d)[0]), "+f"((d)[1]), "+f"((d)[2]), "+f"((d)[3]) \
        : "r"((a)[0]), "r"((a)[1]), "r"((a)[2]), "r"((a)[3]), "r"(b0), "r"(b1))

#define SWZ(row, chunk) ((uint32_t)((row) * 128 + (((chunk) ^ ((row) & 7)) << 4)))

// ---------------- kernel 0: zero bucket counts ----------------
__global__ void zero_counts_kernel() {
    if (threadIdx.x < E_NUM) g_counts[threadIdx.x] = 0;
}

__device__ __forceinline__ float softplus_stable(float z) {
    return fmaxf(z, 0.0f) + log1pf(expf(-fabsf(z)));
}

// ---------------- kernel 1: FUSED gating + x-split + W transpose/cast ----------
#define GATE_BLKS (B_TOK / 8)

__device__ void gating_block(const float* __restrict__ x,
                             const float* __restrict__ noise,
                             const float* __restrict__ w_gate,
                             const float* __restrict__ w_noise,
                             int bx) {
    const int warp = threadIdx.x >> 5;
    const int lane = threadIdx.x & 31;
    const int b = bx * 8 + warp;

    float accC[8] = {0.f,0.f,0.f,0.f,0.f,0.f,0.f,0.f};
    float accN[8] = {0.f,0.f,0.f,0.f,0.f,0.f,0.f,0.f};
    const float* xr = x + (size_t)b * D_DIM;
    __half2* xh = (__half2*)(g_xhi + (size_t)b * D_DIM);

    #pragma unroll
    for (int i = 0; i < 16; i++) {
        int d = 2 * lane + 64 * i;
        float2 v = *(const float2*)(xr + d);

        xh[d >> 1] = __halves2half2(__float2half_rn(v.x), __float2half_rn(v.y));

        const float4* wg0 = reinterpret_cast<const float4*>(w_gate  + (size_t)d * 8);
        const float4* wn0 = reinterpret_cast<const float4*>(w_noise + (size_t)d * 8);
        float4 ga = wg0[0], gb = wg0[1], gc = wg0[2], gd = wg0[3];
        float4 na = wn0[0], nb = wn0[1], nc = wn0[2], nd = wn0[3];
        accC[0] = fmaf(v.x, ga.x, accC[0]); accC[1] = fmaf(v.x, ga.y, accC[1]);
        accC[2] = fmaf(v.x, ga.z, accC[2]); accC[3] = fmaf(v.x, ga.w, accC[3]);
        accC[4] = fmaf(v.x, gb.x, accC[4]); accC[5] = fmaf(v.x, gb.y, accC[5]);
        accC[6] = fmaf(v.x, gb.z, accC[6]); accC[7] = fmaf(v.x, gb.w, accC[7]);
        accC[0] = fmaf(v.y, gc.x, accC[0]); accC[1] = fmaf(v.y, gc.y, accC[1]);
        accC[2] = fmaf(v.y, gc.z, accC[2]); accC[3] = fmaf(v.y, gc.w, accC[3]);
        accC[4] = fmaf(v.y, gd.x, accC[4]); accC[5] = fmaf(v.y, gd.y, accC[5]);
        accC[6] = fmaf(v.y, gd.z, accC[6]); accC[7] = fmaf(v.y, gd.w, accC[7]);
        accN[0] = fmaf(v.x, na.x, accN[0]); accN[1] = fmaf(v.x, na.y, accN[1]);
        accN[2] = fmaf(v.x, na.z, accN[2]); accN[3] = fmaf(v.x, na.w, accN[3]);
        accN[4] = fmaf(v.x, nb.x, accN[4]); accN[5] = fmaf(v.x, nb.y, accN[5]);
        accN[6] = fmaf(v.x, nb.z, accN[6]); accN[7] = fmaf(v.x, nb.w, accN[7]);
        accN[0] = fmaf(v.y, nc.x, accN[0]); accN[1] = fmaf(v.y, nc.y, accN[1]);
        accN[2] = fmaf(v.y, nc.z, accN[2]); accN[3] = fmaf(v.y, nc.w, accN[3]);
        accN[4] = fmaf(v.y, nd.x, accN[4]); accN[5] = fmaf(v.y, nd.y, accN[5]);
        accN[6] = fmaf(v.y, nd.z, accN[6]); accN[7] = fmaf(v.y, nd.w, accN[7]);
    }

    #pragma unroll
    for (int e = 0; e < 8; e++) {
        #pragma unroll
        for (int off = 16; off > 0; off >>= 1) {
            accC[e] += __shfl_xor_sync(0xffffffffu, accC[e], off);
            accN[e] += __shfl_xor_sync(0xffffffffu, accN[e], off);
        }
    }

    if (lane == 0) {
        float logits[8];
        #pragma unroll
        for (int e = 0; e < 8; e++) {
            float sd = softplus_stable(accN[e]) + 0.01f;
            logits[e] = fmaf(noise[(size_t)b * E_NUM + e], sd, accC[e]);
        }
        int i0 = 0; float v0 = logits[0];
        #pragma unroll
        for (int e = 1; e < 8; e++) { if (logits[e] > v0) { v0 = logits[e]; i0 = e; } }
        int i1 = -1; float v1 = -INFINITY;
        #pragma unroll
        for (int e = 0; e < 8; e++) {
            if (e != i0 && logits[e] > v1) { v1 = logits[e]; i1 = e; }
        }
        float ex = expf(v1 - v0);
        float inv = 1.0f / (1.0f + ex);
        g_gate[b * 2 + 0] = inv;
        g_gate[b * 2 + 1] = ex * inv;

        int p0 = atomicAdd(&g_counts[i0], 1);
        g_bucket_tok [i0 * B_TOK + p0] = b;
        g_bucket_slot[i0 * B_TOK + p0] = b * 2 + 0;
        int p1 = atomicAdd(&g_counts[i1], 1);
        g_bucket_tok [i1 * B_TOK + p1] = b;
        g_bucket_slot[i1 * B_TOK + p1] = b * 2 + 1;
    }
}

__device__ void prep_w_block(const float* __restrict__ W, int t) {
    __shared__ float tile[32][33];
    const int e   = t >> 10;
    const int rem = t & 1023;
    const int k0  = (rem >> 5) * 32;
    const int n0  = (rem & 31) * 32;
    const int tx  = threadIdx.x & 31;
    const int ty  = threadIdx.x >> 5;  // 0..7
    const float* We = W + (size_t)e * D_DIM * D_DIM;

    #pragma unroll
    for (int i = 0; i < 32; i += 8)
        tile[ty + i][tx] = We[(size_t)(k0 + ty + i) * D_DIM + n0 + tx];
    __syncthreads();

    #pragma unroll
    for (int i = 0; i < 32; i += 8) {
        float v = tile[tx][ty + i];
        size_t o = ((size_t)(e * D_DIM + n0 + ty + i)) * D_DIM + k0 + tx;
        g_whi[o] = __float2half_rn(v);
    }
}

__global__ __launch_bounds__(256)
void prep_fused_kernel(const float* __restrict__ x,
                       const float* __restrict__ noise,
                       const float* __restrict__ w_gate,
                       const float* __restrict__ w_noise,
                       const float* __restrict__ W) {
    const int bx = blockIdx.x;
    if (bx < GATE_BLKS) gating_block(x, noise, w_gate, w_noise, bx);
    else                prep_w_block(W, bx - GATE_BLKS);
}

// ---------------- kernel 2: routed 1-pass fp16 GEMM (128x128, 2 CTAs/SM) ------
#define BMh 128
#define BNh 128
#define BKh 64
#define NCHUNK (D_DIM / BKh)           // 16
#define STG 32768                      // A 16K | B 16K
#define OFF_B 16384
#define NSTAGE 3
#define NTHR 256
#define SMEM_GEMM (1024 + NSTAGE * STG)

__device__ __forceinline__ void load_stage(uint32_t sbuf, const int* stok,
                                           const __half* __restrict__ wh,
                                           int kt, int tid) {
    #pragma unroll
    for (int i = 0; i < 4; i++) {              // A: 128 rows x 8 chunks
        int lin = i * NTHR + tid;
        int row = lin >> 3, ch = lin & 7;
        int tok = stok[row];
        const __half* sa = g_xhi + (size_t)tok * D_DIM + kt + ch * 8;
        CP16(sbuf + SWZ(row, ch), sa);
    }
    #pragma unroll
    for (int i = 0; i < 4; i++) {              // B: 128 rows x 8 chunks
        int lin = i * NTHR + tid;
        int row = lin >> 3, ch = lin & 7;
        const __half* sb = wh + (size_t)row * D_DIM + kt + ch * 8;
        CP16(sbuf + OFF_B + SWZ(row, ch), sb);
    }
}

__global__ __launch_bounds__(NTHR, 2)
void expert_hmma_kernel(const float* __restrict__ bias) {
    const int e     = blockIdx.z;
    const int count = g_counts[e];
    const int m0    = blockIdx.y * BMh;
    if (m0 >= count) return;
    const int n0    = blockIdx.x * BNh;

    extern __shared__ char smraw[];
    int* stok  = (int*)smraw;            // [128]
    int* sslot = (int*)(smraw + 512);    // [128]
    const uint32_t sbase = smem_u32(smraw) + 1024;
    uint32_t sbuf3[NSTAGE];
    #pragma unroll
    for (int s = 0; s < NSTAGE; s++) sbuf3[s] = sbase + s * STG;

    const int tid  = threadIdx.x;
    const int wid  = tid >> 5;
    const int lane = tid & 31;
    const int wm   = (wid & 3) * 32;     // 4 warps over 128 m
    const int wn   = (wid >> 2) * 64;    // 2 warps over 128 n

    if (tid < BMh) {
        int m = m0 + tid;
        bool ok = (m < count);
        stok [tid] = ok ? g_bucket_tok [e * B_TOK + m] : 0;
        sslot[tid] = ok ? g_bucket_slot[e * B_TOK + m] : -1;
    }
    __syncthreads();

    const __half* wh = g_whi + ((size_t)e * D_DIM + n0) * D_DIM;

    float acc[2][8][4];
    #pragma unroll
    for (int mt = 0; mt < 2; mt++)
        #pragma unroll
        for (int nt = 0; nt < 8; nt++)
            #pragma unroll
            for (int c = 0; c < 4; c++) acc[mt][nt][c] = 0.0f;

    load_stage(sbuf3[0], stok, wh, 0, tid);
    CP_COMMIT();
    load_stage(sbuf3[1], stok, wh, BKh, tid);
    CP_COMMIT();

    const int lrow = lane & 15;
    const int lsel = lane >> 4;

    int sidx = 0;
    int pidx = 2;
    for (int c = 0; c < NCHUNK; c++) {
        if (c == NCHUNK - 1) { CP_WAIT0(); } else { CP_WAIT1(); }
        __syncthreads();
        if (c + 2 < NCHUNK) {
            load_stage(sbuf3[pidx], stok, wh, (c + 2) * BKh, tid);
            CP_COMMIT();
        }

        const uint32_t sbuf = sbuf3[sidx];
        #pragma unroll
        for (int ks = 0; ks < 4; ks++) {
            const int chunk = ks * 2 + lsel;
            uint32_t ahi[2][4];
            #pragma unroll
            for (int mt = 0; mt < 2; mt++) {
                int r = wm + mt * 16 + lrow;
                LDSM4(ahi[mt], sbuf + SWZ(r, chunk));
            }
            #pragma unroll
            for (int ng = 0; ng < 4; ng++) {           // 4 n16-groups over wn..wn+63
                int r = wn + ng * 16 + lrow;
                uint32_t bhi[4];
                LDSM4(bhi, sbuf + OFF_B + SWZ(r, chunk));
                #pragma unroll
                for (int mt = 0; mt < 2; mt++) {
                    #pragma unroll
                    for (int o = 0; o < 2; o++)
                        MMA16816(acc[mt][ng * 2 + o], ahi[mt], bhi[o], bhi[2 + o]);
                }
            }
        }

        sidx = (sidx + 1 == NSTAGE) ? 0 : sidx + 1;
        pidx = (pidx + 1 == NSTAGE) ? 0 : pidx + 1;
    }

    // epilogue: fused bias + exp, scatter to per-slot partials
    #pragma unroll
    for (int mt = 0; mt < 2; mt++) {
        #pragma unroll
        for (int h = 0; h < 2; h++) {
            int m = wm + mt * 16 + (lane >> 2) + h * 8;
            int slot = sslot[m];
            if (slot < 0) continue;
            float* pr = g_partial + ((size_t)slot << 10);
            #pragma unroll
            for (int nt = 0; nt < 8; nt++) {
                int col = n0 + wn + nt * 8 + (lane & 3) * 2;
                float2 bv = *(const float2*)(bias + (size_t)e * D_DIM + col);
                float2 o;
                o.x = expf(acc[mt][nt][h * 2 + 0] + bv.x);
                o.y = expf(acc[mt][nt][h * 2 + 1] + bv.y);
                *(float2*)(pr + col) = o;
            }
        }
    }
}

// ---------------- kernel 3: combine ----------------
__global__ void combine_kernel(float* __restrict__ out) {
    int idx = blockIdx.x * 256 + threadIdx.x;
    int b = idx >> 8;
    int h4 = (idx & 255) << 2;
    float g0 = g_gate[b * 2 + 0];
    float g1 = g_gate[b * 2 + 1];
    float4 p0 = *(const float4*)(g_partial + ((size_t)(b * 2 + 0) << 10) + h4);
    float4 p1 = *(const float4*)(g_partial + ((size_t)(b * 2 + 1) << 10) + h4);
    float4 o;
    float c0 = fmaf(g0, p0.x, g1 * p1.x);
    float c1 = fmaf(g0, p0.y, g1 * p1.y);
    float c2 = fmaf(g0, p0.z, g1 * p1.z);
    float c3 = fmaf(g0, p0.w, g1 * p1.w);
    const float EPSF = 2.2204460492503131e-16f;
    o.x = logf(c0 == 0.0f ? EPSF : c0);
    o.y = logf(c1 == 0.0f ? EPSF : c1);
    o.z = logf(c2 == 0.0f ? EPSF : c2);
    o.w = logf(c3 == 0.0f ? EPSF : c3);
    *(float4*)(out + (size_t)b * D_DIM + h4) = o;
}

// ---------------- launch ----------------
extern "C" void kernel_launch(void* const* d_in, const int* in_sizes, int n_in,
                              void* d_out, int out_size) {
    const float* x         = (const float*)d_in[0];
    const float* noise     = (const float*)d_in[1];
    const float* w_gate    = (const float*)d_in[2];
    const float* w_noise   = (const float*)d_in[3];
    const float* W_experts = (const float*)d_in[4];
    const float* b_experts = (const float*)d_in[5];
    float* out = (float*)d_out;

    cudaFuncSetAttribute(expert_hmma_kernel,
                         cudaFuncAttributeMaxDynamicSharedMemorySize, SMEM_GEMM);

    zero_counts_kernel<<<1, 32>>>();
    prep_fused_kernel<<<GATE_BLKS + 8192, 256>>>(x, noise, w_gate, w_noise, W_experts);

    dim3 ggrid(D_DIM / BNh, B_TOK / BMh, E_NUM);  // (8, 64, 8)
    expert_hmma_kernel<<<ggrid, NTHR, SMEM_GEMM>>>(b_experts);

    combine_kernel<<<(B_TOK * D_DIM / 4) / 256, 256>>>(out);
}

// round 10
// speedup vs baseline: 2.0079x; 1.0082x over previous
#include <cuda_runtime.h>
#include <cuda_fp16.h>
#include <math.h>
#include <stdint.h>

#define B_TOK 8192
#define D_DIM 1024
#define E_NUM 8

// ---------------- scratch (device globals; no allocs allowed) ----------------
__device__ int    g_counts[E_NUM];   // static-zero-init; reset by combine_kernel each call
__device__ int    g_bucket_tok [E_NUM * B_TOK];
__device__ int    g_bucket_slot[E_NUM * B_TOK];
__device__ float  g_gate[B_TOK * 2];
__device__ float  g_partial[(size_t)B_TOK * 2 * D_DIM];       // exp(expert_out) per slot
__device__ __half g_xhi[(size_t)B_TOK * D_DIM];
__device__ __half g_whi[(size_t)E_NUM * D_DIM * D_DIM];       // W^T fp16, [E][N][K]

// ---------------- PTX helpers (sm_80-baseline only) ----------------
__device__ __forceinline__ uint32_t smem_u32(const void* p) {
    uint32_t a;
    asm("{ .reg .u64 t; cvta.to.shared.u64 t, %1; cvt.u32.u64 %0, t; }" : "=r"(a) : "l"(p));
    return a;
}

#define CP16(dst, src) \
    asm volatile("cp.async.cg.shared.global [%0], [%1], 16;" \
        :: "r"(dst), "l"(__cvta_generic_to_global(src)) : "memory")
#define CP_COMMIT() asm volatile("cp.async.commit_group;" ::: "memory")
#define CP_WAIT1()  asm volatile("cp.async.wait_group 1;" ::: "memory")
#define CP_WAIT0()  asm volatile("cp.async.wait_group 0;" ::: "memory")

#define LDSM4(r, addr) \
    asm volatile("ldmatrix.sync.aligned.m8n8.x4.shared.b16 {%0,%1,%2,%3}, [%4];" \
        : "=r"((r)[0]), "=r"((r)[1]), "=r"((r)[2]), "=r"((r)[3]) : "r"(addr))

#define MMA16816(d, a, b0, b1) \
    asm volatile("mma.sync.aligned.m16n8k16.row.col.f32.f16.f16.f32 " \
        "{%0,%1,%2,%3}, {%4,%5,%6,%7}, {%8,%9}, {%0,%1,%2,%3};" \
        : "+f"((d)[0]), "+f"((d)[1]), "+f"((d)[2]), "+f"((d)[3]) \
        : "r"((a)[0]), "r"((a)[1]), "r"((a)[2]), "r"((a)[3]), "r"(b0), "r"(b1))

#define SWZ(row, chunk) ((uint32_t)((row) * 128 + (((chunk) ^ ((row) & 7)) << 4)))

__device__ __forceinline__ float softplus_stable(float z) {
    return fmaxf(z, 0.0f) + log1pf(expf(-fabsf(z)));
}

// ---------------- kernel 1: FUSED gating + x-split + W transpose/cast ----------
#define GATE_BLKS (B_TOK / 8)

__device__ void gating_block(const float* __restrict__ x,
                             const float* __restrict__ noise,
                             const float* __restrict__ w_gate,
                             const float* __restrict__ w_noise,
                             int bx) {
    const int warp = threadIdx.x >> 5;
    const int lane = threadIdx.x & 31;
    const int b = bx * 8 + warp;

    float accC[8] = {0.f,0.f,0.f,0.f,0.f,0.f,0.f,0.f};
    float accN[8] = {0.f,0.f,0.f,0.f,0.f,0.f,0.f,0.f};
    const float* xr = x + (size_t)b * D_DIM;
    __half2* xh = (__half2*)(g_xhi + (size_t)b * D_DIM);

    #pragma unroll
    for (int i = 0; i < 16; i++) {
        int d = 2 * lane + 64 * i;
        float2 v = *(const float2*)(xr + d);

        xh[d >> 1] = __halves2half2(__float2half_rn(v.x), __float2half_rn(v.y));

        const float4* wg0 = reinterpret_cast<const float4*>(w_gate  + (size_t)d * 8);
        const float4* wn0 = reinterpret_cast<const float4*>(w_noise + (size_t)d * 8);
        float4 ga = wg0[0], gb = wg0[1], gc = wg0[2], gd = wg0[3];
        float4 na = wn0[0], nb = wn0[1], nc = wn0[2], nd = wn0[3];
        accC[0] = fmaf(v.x, ga.x, accC[0]); accC[1] = fmaf(v.x, ga.y, accC[1]);
        accC[2] = fmaf(v.x, ga.z, accC[2]); accC[3] = fmaf(v.x, ga.w, accC[3]);
        accC[4] = fmaf(v.x, gb.x, accC[4]); accC[5] = fmaf(v.x, gb.y, accC[5]);
        accC[6] = fmaf(v.x, gb.z, accC[6]); accC[7] = fmaf(v.x, gb.w, accC[7]);
        accC[0] = fmaf(v.y, gc.x, accC[0]); accC[1] = fmaf(v.y, gc.y, accC[1]);
        accC[2] = fmaf(v.y, gc.z, accC[2]); accC[3] = fmaf(v.y, gc.w, accC[3]);
        accC[4] = fmaf(v.y, gd.x, accC[4]); accC[5] = fmaf(v.y, gd.y, accC[5]);
        accC[6] = fmaf(v.y, gd.z, accC[6]); accC[7] = fmaf(v.y, gd.w, accC[7]);
        accN[0] = fmaf(v.x, na.x, accN[0]); accN[1] = fmaf(v.x, na.y, accN[1]);
        accN[2] = fmaf(v.x, na.z, accN[2]); accN[3] = fmaf(v.x, na.w, accN[3]);
        accN[4] = fmaf(v.x, nb.x, accN[4]); accN[5] = fmaf(v.x, nb.y, accN[5]);
        accN[6] = fmaf(v.x, nb.z, accN[6]); accN[7] = fmaf(v.x, nb.w, accN[7]);
        accN[0] = fmaf(v.y, nc.x, accN[0]); accN[1] = fmaf(v.y, nc.y, accN[1]);
        accN[2] = fmaf(v.y, nc.z, accN[2]); accN[3] = fmaf(v.y, nc.w, accN[3]);
        accN[4] = fmaf(v.y, nd.x, accN[4]); accN[5] = fmaf(v.y, nd.y, accN[5]);
        accN[6] = fmaf(v.y, nd.z, accN[6]); accN[7] = fmaf(v.y, nd.w, accN[7]);
    }

    #pragma unroll
    for (int e = 0; e < 8; e++) {
        #pragma unroll
        for (int off = 16; off > 0; off >>= 1) {
            accC[e] += __shfl_xor_sync(0xffffffffu, accC[e], off);
            accN[e] += __shfl_xor_sync(0xffffffffu, accN[e], off);
        }
    }

    if (lane == 0) {
        float logits[8];
        #pragma unroll
        for (int e = 0; e < 8; e++) {
            float sd = softplus_stable(accN[e]) + 0.01f;
            logits[e] = fmaf(noise[(size_t)b * E_NUM + e], sd, accC[e]);
        }
        int i0 = 0; float v0 = logits[0];
        #pragma unroll
        for (int e = 1; e < 8; e++) { if (logits[e] > v0) { v0 = logits[e]; i0 = e; } }
        int i1 = -1; float v1 = -INFINITY;
        #pragma unroll
        for (int e = 0; e < 8; e++) {
            if (e != i0 && logits[e] > v1) { v1 = logits[e]; i1 = e; }
        }
        float ex = expf(v1 - v0);
        float inv = 1.0f / (1.0f + ex);
        g_gate[b * 2 + 0] = inv;
        g_gate[b * 2 + 1] = ex * inv;

        int p0 = atomicAdd(&g_counts[i0], 1);
        g_bucket_tok [i0 * B_TOK + p0] = b;
        g_bucket_slot[i0 * B_TOK + p0] = b * 2 + 0;
        int p1 = atomicAdd(&g_counts[i1], 1);
        g_bucket_tok [i1 * B_TOK + p1] = b;
        g_bucket_slot[i1 * B_TOK + p1] = b * 2 + 1;
    }
}

__device__ void prep_w_block(const float* __restrict__ W, int t) {
    __shared__ float tile[32][33];
    const int e   = t >> 10;
    const int rem = t & 1023;
    const int k0  = (rem >> 5) * 32;
    const int n0  = (rem & 31) * 32;
    const int tx  = threadIdx.x & 31;
    const int ty  = threadIdx.x >> 5;  // 0..7
    const float* We = W + (size_t)e * D_DIM * D_DIM;

    #pragma unroll
    for (int i = 0; i < 32; i += 8)
        tile[ty + i][tx] = We[(size_t)(k0 + ty + i) * D_DIM + n0 + tx];
    __syncthreads();

    #pragma unroll
    for (int i = 0; i < 32; i += 8) {
        float v = tile[tx][ty + i];
        size_t o = ((size_t)(e * D_DIM + n0 + ty + i)) * D_DIM + k0 + tx;
        g_whi[o] = __float2half_rn(v);
    }
}

__global__ __launch_bounds__(256)
void prep_fused_kernel(const float* __restrict__ x,
                       const float* __restrict__ noise,
                       const float* __restrict__ w_gate,
                       const float* __restrict__ w_noise,
                       const float* __restrict__ W) {
    const int bx = blockIdx.x;
    if (bx < GATE_BLKS) gating_block(x, noise, w_gate, w_noise, bx);
    else                prep_w_block(W, bx - GATE_BLKS);
}

// ---------------- kernel 2: routed 1-pass fp16 GEMM (128x128, 2 CTAs/SM) ------
#define BMh 128
#define BNh 128
#define BKh 64
#define NCHUNK (D_DIM / BKh)           // 16
#define STG 32768                      // A 16K | B 16K
#define OFF_B 16384
#define NSTAGE 3
#define NTHR 256
#define SMEM_GEMM (1024 + NSTAGE * STG)

__device__ __forceinline__ void load_stage(uint32_t sbuf, const int* stok,
                                           const __half* __restrict__ wh,
                                           int kt, int tid) {
    #pragma unroll
    for (int i = 0; i < 4; i++) {              // A: 128 rows x 8 chunks
        int lin = i * NTHR + tid;
        int row = lin >> 3, ch = lin & 7;
        int tok = stok[row];
        const __half* sa = g_xhi + (size_t)tok * D_DIM + kt + ch * 8;
        CP16(sbuf + SWZ(row, ch), sa);
    }
    #pragma unroll
    for (int i = 0; i < 4; i++) {              // B: 128 rows x 8 chunks
        int lin = i * NTHR + tid;
        int row = lin >> 3, ch = lin & 7;
        const __half* sb = wh + (size_t)row * D_DIM + kt + ch * 8;
        CP16(sbuf + OFF_B + SWZ(row, ch), sb);
    }
}

__global__ __launch_bounds__(NTHR, 2)
void expert_hmma_kernel(const float* __restrict__ bias) {
    const int e     = blockIdx.z;
    const int count = g_counts[e];
    const int m0    = blockIdx.y * BMh;
    if (m0 >= count) return;
    const int n0    = blockIdx.x * BNh;

    extern __shared__ char smraw[];
    int* stok  = (int*)smraw;            // [128]
    int* sslot = (int*)(smraw + 512);    // [128]
    const uint32_t sbase = smem_u32(smraw) + 1024;
    uint32_t sbuf3[NSTAGE];
    #pragma unroll
    for (int s = 0; s < NSTAGE; s++) sbuf3[s] = sbase + s * STG;

    const int tid  = threadIdx.x;
    const int wid  = tid >> 5;
    const int lane = tid & 31;
    const int wm   = (wid & 3) * 32;     // 4 warps over 128 m
    const int wn   = (wid >> 2) * 64;    // 2 warps over 128 n

    if (tid < BMh) {
        int m = m0 + tid;
        bool ok = (m < count);
        stok [tid] = ok ? g_bucket_tok [e * B_TOK + m] : 0;
        sslot[tid] = ok ? g_bucket_slot[e * B_TOK + m] : -1;
    }
    __syncthreads();

    const __half* wh = g_whi + ((size_t)e * D_DIM + n0) * D_DIM;

    float acc[2][8][4];
    #pragma unroll
    for (int mt = 0; mt < 2; mt++)
        #pragma unroll
        for (int nt = 0; nt < 8; nt++)
            #pragma unroll
            for (int c = 0; c < 4; c++) acc[mt][nt][c] = 0.0f;

    load_stage(sbuf3[0], stok, wh, 0, tid);
    CP_COMMIT();
    load_stage(sbuf3[1], stok, wh, BKh, tid);
    CP_COMMIT();

    const int lrow = lane & 15;
    const int lsel = lane >> 4;

    int sidx = 0;
    int pidx = 2;
    for (int c = 0; c < NCHUNK; c++) {
        if (c == NCHUNK - 1) { CP_WAIT0(); } else { CP_WAIT1(); }
        __syncthreads();
        if (c + 2 < NCHUNK) {
            load_stage(sbuf3[pidx], stok, wh, (c + 2) * BKh, tid);
            CP_COMMIT();
        }

        const uint32_t sbuf = sbuf3[sidx];
        #pragma unroll
        for (int ks = 0; ks < 4; ks++) {
            const int chunk = ks * 2 + lsel;
            uint32_t ahi[2][4];
            #pragma unroll
            for (int mt = 0; mt < 2; mt++) {
                int r = wm + mt * 16 + lrow;
                LDSM4(ahi[mt], sbuf + SWZ(r, chunk));
            }
            #pragma unroll
            for (int ng = 0; ng < 4; ng++) {           // 4 n16-groups over wn..wn+63
                int r = wn + ng * 16 + lrow;
                uint32_t bhi[4];
                LDSM4(bhi, sbuf + OFF_B + SWZ(r, chunk));
                #pragma unroll
                for (int mt = 0; mt < 2; mt++) {
                    #pragma unroll
                    for (int o = 0; o < 2; o++)
                        MMA16816(acc[mt][ng * 2 + o], ahi[mt], bhi[o], bhi[2 + o]);
                }
            }
        }

        sidx = (sidx + 1 == NSTAGE) ? 0 : sidx + 1;
        pidx = (pidx + 1 == NSTAGE) ? 0 : pidx + 1;
    }

    // epilogue: fused bias + fast exp, scatter to per-slot partials
    #pragma unroll
    for (int mt = 0; mt < 2; mt++) {
        #pragma unroll
        for (int h = 0; h < 2; h++) {
            int m = wm + mt * 16 + (lane >> 2) + h * 8;
            int slot = sslot[m];
            if (slot < 0) continue;
            float* pr = g_partial + ((size_t)slot << 10);
            #pragma unroll
            for (int nt = 0; nt < 8; nt++) {
                int col = n0 + wn + nt * 8 + (lane & 3) * 2;
                float2 bv = *(const float2*)(bias + (size_t)e * D_DIM + col);
                float2 o;
                o.x = __expf(acc[mt][nt][h * 2 + 0] + bv.x);
                o.y = __expf(acc[mt][nt][h * 2 + 1] + bv.y);
                *(float2*)(pr + col) = o;
            }
        }
    }
}

// ---------------- kernel 3: combine (8 elems/thread, fast log) -----------------
__device__ __forceinline__ float safelog(float c) {
    const float EPSF = 2.2204460492503131e-16f;
    return __logf(c == 0.0f ? EPSF : c);
}

__global__ void combine_kernel(float* __restrict__ out) {
    int idx = blockIdx.x * 256 + threadIdx.x;        // over B*D/8
    int b  = idx >> 7;
    int h8 = (idx & 127) << 3;
    float g0 = g_gate[b * 2 + 0];
    float g1 = g_gate[b * 2 + 1];
    const float* p0p = g_partial + ((size_t)(b * 2 + 0) << 10) + h8;
    const float* p1p = g_partial + ((size_t)(b * 2 + 1) << 10) + h8;
    float4 p0a = *(const float4*)(p0p);
    float4 p0b = *(const float4*)(p0p + 4);
    float4 p1a = *(const float4*)(p1p);
    float4 p1b = *(const float4*)(p1p + 4);
    float4 oa, ob;
    oa.x = safelog(fmaf(g0, p0a.x, g1 * p1a.x));
    oa.y = safelog(fmaf(g0, p0a.y, g1 * p1a.y));
    oa.z = safelog(fmaf(g0, p0a.z, g1 * p1a.z));
    oa.w = safelog(fmaf(g0, p0a.w, g1 * p1a.w));
    ob.x = safelog(fmaf(g0, p0b.x, g1 * p1b.x));
    ob.y = safelog(fmaf(g0, p0b.y, g1 * p1b.y));
    ob.z = safelog(fmaf(g0, p0b.z, g1 * p1b.z));
    ob.w = safelog(fmaf(g0, p0b.w, g1 * p1b.w));
    float* op = out + (size_t)b * D_DIM + h8;
    *(float4*)(op)     = oa;
    *(float4*)(op + 4) = ob;

    // reset bucket counts for the next kernel_launch call (replaces zero_counts)
    if (blockIdx.x == 0 && threadIdx.x < E_NUM) g_counts[threadIdx.x] = 0;
}

// ---------------- launch ----------------
extern "C" void kernel_launch(void* const* d_in, const int* in_sizes, int n_in,
                              void* d_out, int out_size) {
    const float* x         = (const float*)d_in[0];
    const float* noise     = (const float*)d_in[1];
    const float* w_gate    = (const float*)d_in[2];
    const float* w_noise   = (const float*)d_in[3];
    const float* W_experts = (const float*)d_in[4];
    const float* b_experts = (const float*)d_in[5];
    float* out = (float*)d_out;

    cudaFuncSetAttribute(expert_hmma_kernel,
                         cudaFuncAttributeMaxDynamicSharedMemorySize, SMEM_GEMM);

    prep_fused_kernel<<<GATE_BLKS + 8192, 256>>>(x, noise, w_gate, w_noise, W_experts);

    dim3 ggrid(D_DIM / BNh, B_TOK / BMh, E_NUM);  // (8, 64, 8)
    expert_hmma_kernel<<<ggrid, NTHR, SMEM_GEMM>>>(b_experts);

    combine_kernel<<<(B_TOK * D_DIM / 8) / 256, 256>>>(out);
}